// round 9
// baseline (speedup 1.0000x reference)
#include <cuda_runtime.h>
#include <cuda_bf16.h>
#include <cstdint>

// ---------------- Problem constants ----------------
#define QLEN   2048
#define DMODEL 4096
#define NHEAD  32
#define NKVH   8
#define HEADD  128
#define NSINK  4
#define NWIN   2048
#define NSNW   (NSINK + NWIN)          // 2052
#define KTOT   (NSNW + QLEN)           // 4100
#define GRP    (NHEAD / NKVH)          // 4
#define KVDIM  (NKVH * HEADD)          // 1024
#define VSTR   (KTOT + 64)             // 4164 (16B-aligned rows, zero pad tail)

#define NEG_BIG (-3.4028234663852886e38f)   // finfo(float32).min
#define LOG10000_OVER_64 0.14391156831212787f
#define ATTN_SCALE 0.08838834764831845f     // 1/sqrt(128)

// ---------------- Scratch (device globals; no runtime alloc) ----------------
__device__ float g_q[QLEN * DMODEL];        // q proj -> RoPE'd, tf32-rounded
__device__ float g_kproj[QLEN * KVDIM];
__device__ float g_vproj[QLEN * KVDIM];
__device__ float g_K[NKVH * KTOT * HEADD + 64 * HEADD];  // RoPE'd K, d-interleaved, tf32
__device__ float g_Vt[NKVH * HEADD * VSTR];  // V cache TRANSPOSED [kvh][d][key(perm8)], tf32
__device__ float g_attn[QLEN * DMODEL];      // attention output (pre-Wo), raw fp32
__device__ float g_bias[NSNW];               // cache bias (mask * NEG)
__device__ int   g_maxpos;

// tf32-rounded operand copies for cp.async GEMMs
__device__ float g_hidT[QLEN * DMODEL];      // hidden, rounded, perm8 k-interleaved (A op)
__device__ float g_attnT[QLEN * DMODEL];     // attn out, rounded, perm8 (A op)
__device__ float g_WqR[DMODEL * DMODEL];     // weights, rounded (B ops, layout unchanged)
__device__ float g_WkR[DMODEL * KVDIM];
__device__ float g_WvR[DMODEL * KVDIM];
__device__ float g_WoR[DMODEL * DMODEL];

__device__ __forceinline__ float neg_inf() { return __int_as_float(0xff800000u); }

// column interleave within each 8-block: pairs (c, c+4) adjacent
__device__ __forceinline__ int perm8(int d) {
    return (d & ~7) | ((d & 3) << 1) | ((d >> 2) & 1);
}

__device__ __forceinline__ uint32_t f2tf32(float x) {
    uint32_t u;
    asm("cvt.rna.tf32.f32 %0, %1;" : "=r"(u) : "f"(x));
    return u;
}
__device__ __forceinline__ float f2tf32f(float x) {
    return __uint_as_float(f2tf32(x));
}

__device__ __forceinline__ void mma_tf32(float d[4],
                                         uint32_t a0, uint32_t a1, uint32_t a2, uint32_t a3,
                                         uint32_t b0, uint32_t b1) {
    asm volatile(
        "mma.sync.aligned.m16n8k8.row.col.f32.tf32.tf32.f32 "
        "{%0,%1,%2,%3}, {%4,%5,%6,%7}, {%8,%9}, {%0,%1,%2,%3};\n"
        : "+f"(d[0]), "+f"(d[1]), "+f"(d[2]), "+f"(d[3])
        : "r"(a0), "r"(a1), "r"(a2), "r"(a3), "r"(b0), "r"(b1));
}

__device__ __forceinline__ void cp16(uint32_t dst, const float* src, bool v) {
    asm volatile("cp.async.cg.shared.global [%0], [%1], 16, %2;\n"
                 :: "r"(dst), "l"(src), "r"(v ? 16 : 0) : "memory");
}
__device__ __forceinline__ void cp_commit() {
    asm volatile("cp.async.commit_group;\n" ::: "memory");
}
__device__ __forceinline__ void cp_wait0() {
    asm volatile("cp.async.wait_group 0;\n" ::: "memory");
}
__device__ __forceinline__ void cp_wait1() {
    asm volatile("cp.async.wait_group 1;\n" ::: "memory");
}

// ---------------- max position + bias precompute ----------------
__global__ void maxpos_kernel(const int* __restrict__ sink_pos,
                              const int* __restrict__ key_pos) {
    __shared__ int sm[256];
    int tid = threadIdx.x;
    int v = -2147483647;
    for (int i = tid; i < NWIN; i += 256) v = max(v, key_pos[i]);
    for (int i = tid; i < NSINK; i += 256) v = max(v, sink_pos[i]);
    sm[tid] = v;
    __syncthreads();
    for (int s = 128; s > 0; s >>= 1) {
        if (tid < s) sm[tid] = max(sm[tid], sm[tid + s]);
        __syncthreads();
    }
    if (tid == 0) g_maxpos = sm[0] + 1;
}

__global__ void bias_kernel(const float* __restrict__ sink_mask,
                            const float* __restrict__ key_mask) {
    int i = blockIdx.x * blockDim.x + threadIdx.x;
    if (i >= NSNW) return;
    float m = (i < NSINK) ? sink_mask[i] : key_mask[i - NSINK];
    g_bias[i] = m * NEG_BIG;
}

// ---------------- prep: tf32 rounding (+ perm8 for A operands) ----------------
__global__ void round_perm_kernel(const float* __restrict__ src,
                                  float* __restrict__ dst, int n) {
    int i = (blockIdx.x * 256 + threadIdx.x) * 4;
    if (i >= n) return;
    float4 v = *(const float4*)(src + i);
    int base = i & ~7;
    if (i & 4) {            // high half of 8-block -> odd slots
        dst[base + 1] = f2tf32f(v.x);
        dst[base + 3] = f2tf32f(v.y);
        dst[base + 5] = f2tf32f(v.z);
        dst[base + 7] = f2tf32f(v.w);
    } else {                // low half -> even slots
        dst[base + 0] = f2tf32f(v.x);
        dst[base + 2] = f2tf32f(v.y);
        dst[base + 4] = f2tf32f(v.z);
        dst[base + 6] = f2tf32f(v.w);
    }
}

__global__ void round_kernel(const float* __restrict__ src,
                             float* __restrict__ dst, int n) {
    int i = (blockIdx.x * 256 + threadIdx.x) * 4;
    if (i >= n) return;
    float4 v = *(const float4*)(src + i);
    float4 o = {f2tf32f(v.x), f2tf32f(v.y), f2tf32f(v.z), f2tf32f(v.w)};
    *(float4*)(dst + i) = o;
}

// ---------------- TF32 GEMM v2: cp.async, 4 warps, 64x64 warp tile ----------------
// A (pre-rounded, perm8 k-interleaved) [M][K]; B (pre-rounded) [K][N]; C[M][N].
// CTA tile 128x128, k-step 32, 2-stage cp.async double buffer.
#define GA_STR 40                     // A smem row: 32 k-words + 8 pad (mod32 = 8)
#define GB_STR 136                    // B smem row: 128 n-words + 8 pad (mod32 = 8)
#define G_ABYTES (128 * GA_STR * 4)   // 20480
#define G_BBYTES (32 * GB_STR * 4)    // 17408
#define G_STAGE  (G_ABYTES + G_BBYTES)
#define G_SMEM   (2 * G_STAGE)        // 75776

__device__ __forceinline__ void g_stage_load(uint32_t sb, int t,
                                             const float* __restrict__ A,
                                             const float* __restrict__ B,
                                             int N, int cRow, int cCol, int tid) {
    uint32_t ab = sb + (t & 1) * G_STAGE;
    uint32_t bb = ab + G_ABYTES;
    const int k0 = t * 32;
    const float* arow = A + (size_t)(cRow + tid) * DMODEL + k0;
#pragma unroll
    for (int c = 0; c < 8; c++)
        cp16(ab + (tid * GA_STR + c * 4) * 4, arow + c * 4, true);
    const int bk = tid >> 2, bc = (tid & 3) * 32;
    const float* brow = B + (size_t)(k0 + bk) * N + cCol + bc;
#pragma unroll
    for (int c = 0; c < 8; c++)
        cp16(bb + (bk * GB_STR + bc + c * 4) * 4, brow + c * 4, true);
}

__device__ __forceinline__ void gemm_cp_body(
    const float* __restrict__ A, const float* __restrict__ B,
    float* __restrict__ C, int N, int cRow, int cCol, char* smem) {
    const int NSTAGE = DMODEL / 32;            // 128
    const int tid  = threadIdx.x;
    const int lane = tid & 31;
    const int warp = tid >> 5;
    const int wm   = (warp >> 1) * 64;
    const int wn   = (warp & 1) * 64;
    const int r0   = lane >> 2;
    const int cq   = lane & 3;
    const uint32_t sb = (uint32_t)__cvta_generic_to_shared(smem);

    float acc[4][8][4];
#pragma unroll
    for (int mt = 0; mt < 4; mt++)
#pragma unroll
        for (int nt = 0; nt < 8; nt++)
#pragma unroll
            for (int f = 0; f < 4; f++) acc[mt][nt][f] = 0.f;

    g_stage_load(sb, 0, A, B, N, cRow, cCol, tid);
    cp_commit();

    for (int t = 0; t < NSTAGE; t++) {
        if (t + 1 < NSTAGE) {
            g_stage_load(sb, t + 1, A, B, N, cRow, cCol, tid);
            cp_commit();
            cp_wait1();
        } else {
            cp_wait0();
        }
        __syncthreads();

        const uint32_t* As = (const uint32_t*)(smem + (t & 1) * G_STAGE);
        const uint32_t* Bs = (const uint32_t*)(smem + (t & 1) * G_STAGE + G_ABYTES);
#pragma unroll
        for (int kb = 0; kb < 4; kb++) {
            const int kb8 = kb * 8;
            uint32_t a[4][4];
#pragma unroll
            for (int mt = 0; mt < 4; mt++) {
                int mr = wm + mt * 16 + r0;
                uint2 u0 = *(const uint2*)&As[mr * GA_STR + kb8 + 2 * cq];
                uint2 u1 = *(const uint2*)&As[(mr + 8) * GA_STR + kb8 + 2 * cq];
                a[mt][0] = u0.x; a[mt][1] = u1.x;
                a[mt][2] = u0.y; a[mt][3] = u1.y;
            }
#pragma unroll
            for (int nt = 0; nt < 8; nt++) {
                int nc = wn + nt * 8 + r0;
                uint32_t b0 = Bs[(kb8 + cq) * GB_STR + nc];
                uint32_t b1 = Bs[(kb8 + cq + 4) * GB_STR + nc];
#pragma unroll
                for (int mt = 0; mt < 4; mt++)
                    mma_tf32(acc[mt][nt], a[mt][0], a[mt][1], a[mt][2], a[mt][3], b0, b1);
            }
        }
        __syncthreads();
    }

#pragma unroll
    for (int mt = 0; mt < 4; mt++)
#pragma unroll
        for (int nt = 0; nt < 8; nt++) {
            int r = cRow + wm + mt * 16 + r0;
            int c = cCol + wn + nt * 8 + cq * 2;
            float2 v0 = {acc[mt][nt][0], acc[mt][nt][1]};
            float2 v1 = {acc[mt][nt][2], acc[mt][nt][3]};
            *(float2*)(C + (size_t)r * N + c)       = v0;
            *(float2*)(C + (size_t)(r + 8) * N + c) = v1;
        }
}

__global__ void __launch_bounds__(128, 2) gemm_cp(
    const float* __restrict__ A, const float* __restrict__ B,
    float* __restrict__ C, int N) {
    extern __shared__ char smg[];
    gemm_cp_body(A, B, C, N, blockIdx.y * 128, blockIdx.x * 128, smg);
}

// fused Wk|Wv projection: grid (16, 16); x<8 -> K proj, x>=8 -> V proj
__global__ void __launch_bounds__(128, 2) gemm_cp_kv(
    const float* __restrict__ A,
    const float* __restrict__ Bk, const float* __restrict__ Bv,
    float* __restrict__ Ck, float* __restrict__ Cv) {
    extern __shared__ char smg[];
    const bool isV = blockIdx.x >= 8;
    gemm_cp_body(A, isV ? Bv : Bk, isV ? Cv : Ck, KVDIM,
                 blockIdx.y * 128, (blockIdx.x & 7) * 128, smg);
}

// ---------------- RoPE on q (in place, writes tf32-rounded) ----------------
__global__ void rope_q_kernel() {
    int idx = blockIdx.x * blockDim.x + threadIdx.x;
    if (idx >= QLEN * NHEAD * 64) return;
    int i  = idx & 63;
    int hq = idx >> 6;
    int h  = hq & (NHEAD - 1);
    int t  = hq >> 5;
    float* p = g_q + (size_t)t * DMODEL + h * HEADD;
    float pos = (float)(g_maxpos + t);
    float freq = expf(-(float)i * LOG10000_OVER_64);
    float ang = pos * freq;
    float c, s;
    sincosf(ang, &s, &c);
    float x1 = p[i], x2 = p[i + 64];
    p[i]      = f2tf32f(x1 * c - x2 * s);
    p[i + 64] = f2tf32f(x2 * c + x1 * s);
}

// ---------------- Build K (RoPE'd, d-interleaved) and V^T (d-major, key-perm8) ----------------
__global__ void build_cache_kernel(const float* __restrict__ sink_k,
                                   const float* __restrict__ sink_v,
                                   const float* __restrict__ win_k,
                                   const float* __restrict__ win_v,
                                   const int* __restrict__ sink_pos,
                                   const int* __restrict__ key_pos) {
    int idx = blockIdx.x * blockDim.x + threadIdx.x;
    if (idx >= NKVH * KTOT * 64) return;
    int i   = idx & 63;
    int rj  = idx >> 6;
    int j   = rj % KTOT;
    int kvh = rj / KTOT;

    const float* kp;
    const float* vp;
    int pos;
    if (j < NSINK) {
        kp = sink_k + (size_t)(kvh * NSINK + j) * HEADD;
        vp = sink_v + (size_t)(kvh * NSINK + j) * HEADD;
        pos = sink_pos[j];
    } else if (j < NSNW) {
        int w = j - NSINK;
        kp = win_k + (size_t)(kvh * NWIN + w) * HEADD;
        vp = win_v + (size_t)(kvh * NWIN + w) * HEADD;
        pos = key_pos[w];
    } else {
        int t = j - NSNW;
        kp = g_kproj + (size_t)t * KVDIM + kvh * HEADD;
        vp = g_vproj + (size_t)t * KVDIM + kvh * HEADD;
        pos = g_maxpos + t;
    }

    float freq = expf(-(float)i * LOG10000_OVER_64);
    float ang = (float)pos * freq;
    float c, s;
    sincosf(ang, &s, &c);
    float x1 = kp[i], x2 = kp[i + 64];

    size_t out = ((size_t)kvh * KTOT + j) * HEADD;
    g_K[out + perm8(i)]      = f2tf32f(x1 * c - x2 * s);
    g_K[out + perm8(i + 64)] = f2tf32f(x2 * c + x1 * s);

    // V transposed: row = (kvh, d), col = key slot (perm8 within 8-key block)
    int jslot = (j & ~7) | ((j & 3) << 1) | ((j >> 2) & 1);
    size_t vb = (size_t)(kvh * HEADD) * VSTR + jslot;
    g_Vt[vb + (size_t)i * VSTR]        = f2tf32f(vp[i]);
    g_Vt[vb + (size_t)(i + 64) * VSTR] = f2tf32f(vp[i + 64]);
}

// ---------------- Flash attention: cp.async K/V, LDS.64 frags everywhere ----------------
// Smem word layout (dynamic):
//   buf: Ks[64][136] (8704 w) then Vs[128][72] (9216 w)  -> BUF_WORDS = 17920
//   (Q staged at buf1 start during prologue: 17408 w <= 17920)
//   Ps[128][68] @ 2*BUF_WORDS
#define KS_STR 136
#define VT_STR 72
#define PS_STR 68
#define BUF_WORDS (64 * KS_STR + 128 * VT_STR)     // 17920
#define PS_OFF    (2 * BUF_WORDS)                   // 35840
#define ATTN_SMEM_BYTES ((PS_OFF + 128 * PS_STR) * 4)

__global__ void __launch_bounds__(256, 1) attn_mma_kernel() {
    extern __shared__ uint32_t smw[];
    const uint32_t smem_base = (uint32_t)__cvta_generic_to_shared(smw);

    const int h    = blockIdx.x;
    const int kvh  = h >> 2;                              // GRP = 4
    const int qt0  = (gridDim.y - 1 - blockIdx.y) * 128;  // long blocks first
    const int tid  = threadIdx.x;
    const int lane = tid & 31;
    const int warp = tid >> 5;
    const int qw   = warp * 16;
    const int r0   = lane >> 2;
    const int cq   = lane & 3;

    const float* Kg = g_K + (size_t)kvh * KTOT * HEADD;
    const float* Vt = g_Vt + (size_t)(kvh * HEADD) * VSTR;

    int kmax = NSNW + qt0 + 128;
    if (kmax > KTOT) kmax = KTOT;
    const int ntiles = (kmax + 63) >> 6;

    // ---- prefetch tile 0 into buf0 ----
    {
        uint32_t kbase = smem_base;
        uint32_t vbase = smem_base + 64 * KS_STR * 4;
        for (int i = tid; i < 2048; i += 256) {
            int key = i >> 5, c = i & 31;
            cp16(kbase + (key * KS_STR + c * 4) * 4, Kg + (size_t)key * HEADD + c * 4, true);
        }
        for (int i = tid; i < 2048; i += 256) {
            int d = i >> 4, c = i & 15;
            cp16(vbase + (d * VT_STR + c * 4) * 4, Vt + (size_t)d * VSTR + c * 4, true);
        }
        cp_commit();
    }

    // ---- stage Q tile [128q][128d] into buf1 region, d-interleaved ----
    {
        uint32_t* Qs = smw + BUF_WORDS;
        const float* qg = g_q + (size_t)qt0 * DMODEL + h * HEADD;
        for (int i = tid; i < 128 * 32; i += 256) {
            int q = i >> 5, c4 = (i & 31) * 4;
            float4 v = *(const float4*)(qg + (size_t)q * DMODEL + c4);
            uint32_t* qrow = Qs + q * KS_STR;
            qrow[perm8(c4 + 0)] = __float_as_uint(v.x);
            qrow[perm8(c4 + 1)] = __float_as_uint(v.y);
            qrow[perm8(c4 + 2)] = __float_as_uint(v.z);
            qrow[perm8(c4 + 3)] = __float_as_uint(v.w);
        }
    }
    __syncthreads();

    // ---- extract Q fragments to registers (LDS.64 pairs) ----
    uint32_t QA[16][4];
    {
        const uint32_t* Qs = smw + BUF_WORDS;
#pragma unroll
        for (int kk = 0; kk < 16; kk++) {
            uint2 u0 = *(const uint2*)&Qs[(qw + r0) * KS_STR + kk * 8 + 2 * cq];
            uint2 u1 = *(const uint2*)&Qs[(qw + r0 + 8) * KS_STR + kk * 8 + 2 * cq];
            QA[kk][0] = u0.x; QA[kk][1] = u1.x;
            QA[kk][2] = u0.y; QA[kk][3] = u1.y;
        }
    }
    __syncthreads();

    float O[16][4];
#pragma unroll
    for (int nt = 0; nt < 16; nt++)
#pragma unroll
        for (int f = 0; f < 4; f++) O[nt][f] = 0.f;
    float m0 = neg_inf(), m1 = neg_inf(), l0 = 0.f, l1 = 0.f;

    const int q0 = qt0 + qw + r0;
    const int q1 = q0 + 8;

    for (int t = 0; t < ntiles; t++) {
        const int j0 = t * 64;
        const int buf = t & 1;
        const uint32_t* Ks = smw + buf * BUF_WORDS;
        const uint32_t* Vs = Ks + 64 * KS_STR;
        uint32_t* Ps = smw + PS_OFF;

        cp_wait0();
        __syncthreads();

        if (t + 1 < ntiles) {
            const int jn = j0 + 64;
            uint32_t kbase = smem_base + (buf ^ 1) * BUF_WORDS * 4;
            uint32_t vbase = kbase + 64 * KS_STR * 4;
            for (int i = tid; i < 2048; i += 256) {
                int key = i >> 5, c = i & 31;
                int j = jn + key;
                bool v = (j < KTOT);
                int jc = v ? j : (KTOT - 1);
                cp16(kbase + (key * KS_STR + c * 4) * 4, Kg + (size_t)jc * HEADD + c * 4, v);
            }
            for (int i = tid; i < 2048; i += 256) {
                int d = i >> 4, c = i & 15;
                cp16(vbase + (d * VT_STR + c * 4) * 4, Vt + (size_t)d * VSTR + jn + c * 4, true);
            }
            cp_commit();
        }

        float bb[8][2];
#pragma unroll
        for (int nt = 0; nt < 8; nt++) {
            int ja = j0 + nt * 8 + cq * 2;
            bb[nt][0] = (ja < NSNW) ? g_bias[ja] : 0.f;
            bb[nt][1] = (ja + 1 < NSNW) ? g_bias[ja + 1] : 0.f;
        }

        // ---- S = Q @ K^T ----
        float S[8][4];
#pragma unroll
        for (int nt = 0; nt < 8; nt++)
#pragma unroll
            for (int f = 0; f < 4; f++) S[nt][f] = 0.f;

        uint2 bc[8];
#pragma unroll
        for (int nt = 0; nt < 8; nt++)
            bc[nt] = *(const uint2*)&Ks[(nt * 8 + r0) * KS_STR + 2 * cq];

#pragma unroll
        for (int kk = 0; kk < 16; kk++) {
            uint2 bn[8];
            if (kk < 15) {
#pragma unroll
                for (int nt = 0; nt < 8; nt++)
                    bn[nt] = *(const uint2*)&Ks[(nt * 8 + r0) * KS_STR + (kk + 1) * 8 + 2 * cq];
            }
#pragma unroll
            for (int nt = 0; nt < 8; nt++)
                mma_tf32(S[nt], QA[kk][0], QA[kk][1], QA[kk][2], QA[kk][3],
                         bc[nt].x, bc[nt].y);
            if (kk < 15) {
#pragma unroll
                for (int nt = 0; nt < 8; nt++) bc[nt] = bn[nt];
            }
        }

        // ---- online softmax ----
        float rm0 = neg_inf(), rm1 = neg_inf();
#pragma unroll
        for (int nt = 0; nt < 8; nt++) {
            int ja = j0 + nt * 8 + cq * 2;
            int jb = ja + 1;
            float s0 = (ja <= q0 + NSNW) ? S[nt][0] * ATTN_SCALE + bb[nt][0] : neg_inf();
            float s1 = (jb <= q0 + NSNW) ? S[nt][1] * ATTN_SCALE + bb[nt][1] : neg_inf();
            float s2 = (ja <= q1 + NSNW) ? S[nt][2] * ATTN_SCALE + bb[nt][0] : neg_inf();
            float s3 = (jb <= q1 + NSNW) ? S[nt][3] * ATTN_SCALE + bb[nt][1] : neg_inf();
            S[nt][0] = s0; S[nt][1] = s1; S[nt][2] = s2; S[nt][3] = s3;
            rm0 = fmaxf(rm0, fmaxf(s0, s1));
            rm1 = fmaxf(rm1, fmaxf(s2, s3));
        }
        rm0 = fmaxf(rm0, __shfl_xor_sync(0xffffffffu, rm0, 1));
        rm0 = fmaxf(rm0, __shfl_xor_sync(0xffffffffu, rm0, 2));
        rm1 = fmaxf(rm1, __shfl_xor_sync(0xffffffffu, rm1, 1));
        rm1 = fmaxf(rm1, __shfl_xor_sync(0xffffffffu, rm1, 2));

        float mn0 = fmaxf(m0, rm0);
        float mn1 = fmaxf(m1, rm1);
        float mns0 = (mn0 == neg_inf()) ? 0.f : mn0;
        float mns1 = (mn1 == neg_inf()) ? 0.f : mn1;
        float f0 = __expf(m0 - mns0);
        float f1 = __expf(m1 - mns1);
        if (m0 == neg_inf()) f0 = 0.f;
        if (m1 == neg_inf()) f1 = 0.f;
        m0 = mn0; m1 = mn1;
        l0 *= f0; l1 *= f1;
#pragma unroll
        for (int nt = 0; nt < 16; nt++) {
            O[nt][0] *= f0; O[nt][1] *= f0;
            O[nt][2] *= f1; O[nt][3] *= f1;
        }

        float ps0 = 0.f, ps1 = 0.f;
#pragma unroll
        for (int nt = 0; nt < 8; nt++) {
            int col = nt * 8 + cq * 2;
            float p0 = __expf(S[nt][0] - mns0);
            float p1 = __expf(S[nt][1] - mns0);
            float p2 = __expf(S[nt][2] - mns1);
            float p3 = __expf(S[nt][3] - mns1);
            ps0 += p0 + p1;
            ps1 += p2 + p3;
            *(uint2*)&Ps[(qw + r0) * PS_STR + col]     = make_uint2(f2tf32(p0), f2tf32(p1));
            *(uint2*)&Ps[(qw + r0 + 8) * PS_STR + col] = make_uint2(f2tf32(p2), f2tf32(p3));
        }
        ps0 += __shfl_xor_sync(0xffffffffu, ps0, 1);
        ps0 += __shfl_xor_sync(0xffffffffu, ps0, 2);
        ps1 += __shfl_xor_sync(0xffffffffu, ps1, 1);
        ps1 += __shfl_xor_sync(0xffffffffu, ps1, 2);
        l0 += ps0; l1 += ps1;

        __syncwarp();

        // ---- O += P @ V (Vs is [d][key-slot]; LDS.64 pairs) ----
        uint32_t ac[4];
        ac[0] = Ps[(qw + r0) * PS_STR + cq];
        ac[1] = Ps[(qw + r0 + 8) * PS_STR + cq];
        ac[2] = Ps[(qw + r0) * PS_STR + cq + 4];
        ac[3] = Ps[(qw + r0 + 8) * PS_STR + cq + 4];
#pragma unroll
        for (int kk = 0; kk < 8; kk++) {
            const int kb = kk * 8;
            uint32_t an[4];
            if (kk < 7) {
                an[0] = Ps[(qw + r0) * PS_STR + kb + 8 + cq];
                an[1] = Ps[(qw + r0 + 8) * PS_STR + kb + 8 + cq];
                an[2] = Ps[(qw + r0) * PS_STR + kb + 8 + cq + 4];
                an[3] = Ps[(qw + r0 + 8) * PS_STR + kb + 8 + cq + 4];
            }
#pragma unroll
            for (int nt = 0; nt < 16; nt++) {
                uint2 vv = *(const uint2*)&Vs[(nt * 8 + r0) * VT_STR + kb + 2 * cq];
                mma_tf32(O[nt], ac[0], ac[1], ac[2], ac[3], vv.x, vv.y);
            }
            if (kk < 7) {
                ac[0] = an[0]; ac[1] = an[1]; ac[2] = an[2]; ac[3] = an[3];
            }
        }
    }

    float inv0 = 1.f / l0, inv1 = 1.f / l1;
    float* og = g_attn + (size_t)h * HEADD;
#pragma unroll
    for (int nt = 0; nt < 16; nt++) {
        int c = nt * 8 + cq * 2;
        float2 v0 = {O[nt][0] * inv0, O[nt][1] * inv0};
        float2 v1 = {O[nt][2] * inv1, O[nt][3] * inv1};
        *(float2*)(og + (size_t)q0 * DMODEL + c) = v0;
        *(float2*)(og + (size_t)q1 * DMODEL + c) = v1;
    }
}

// ---------------- launch ----------------
extern "C" void kernel_launch(void* const* d_in, const int* in_sizes, int n_in,
                              void* d_out, int out_size) {
    const float* hidden    = (const float*)d_in[0];
    const float* sink_k    = (const float*)d_in[1];
    const float* sink_v    = (const float*)d_in[2];
    const float* win_k     = (const float*)d_in[3];
    const float* win_v     = (const float*)d_in[4];
    const int*   sink_pos  = (const int*)d_in[5];
    const int*   key_pos   = (const int*)d_in[6];
    const float* sink_mask = (const float*)d_in[7];
    const float* key_mask  = (const float*)d_in[8];
    const float* Wq        = (const float*)d_in[9];
    const float* Wk        = (const float*)d_in[10];
    const float* Wv        = (const float*)d_in[11];
    const float* Wo        = (const float*)d_in[12];
    float*       out       = (float*)d_out;

    float *pq, *pk, *pv, *pattn, *phidT, *pattnT, *pWqR, *pWkR, *pWvR, *pWoR;
    cudaGetSymbolAddress((void**)&pq, g_q);
    cudaGetSymbolAddress((void**)&pk, g_kproj);
    cudaGetSymbolAddress((void**)&pv, g_vproj);
    cudaGetSymbolAddress((void**)&pattn, g_attn);
    cudaGetSymbolAddress((void**)&phidT, g_hidT);
    cudaGetSymbolAddress((void**)&pattnT, g_attnT);
    cudaGetSymbolAddress((void**)&pWqR, g_WqR);
    cudaGetSymbolAddress((void**)&pWkR, g_WkR);
    cudaGetSymbolAddress((void**)&pWvR, g_WvR);
    cudaGetSymbolAddress((void**)&pWoR, g_WoR);

    static bool attr_set = false;
    if (!attr_set) {
        cudaFuncSetAttribute(attn_mma_kernel,
                             cudaFuncAttributeMaxDynamicSharedMemorySize,
                             ATTN_SMEM_BYTES);
        cudaFuncSetAttribute(gemm_cp,
                             cudaFuncAttributeMaxDynamicSharedMemorySize, G_SMEM);
        cudaFuncSetAttribute(gemm_cp_kv,
                             cudaFuncAttributeMaxDynamicSharedMemorySize, G_SMEM);
        attr_set = true;
    }

    maxpos_kernel<<<1, 256>>>(sink_pos, key_pos);
    bias_kernel<<<(NSNW + 255) / 256, 256>>>(sink_mask, key_mask);

    // prep: tf32-rounded operand copies
    const int EL4 = 256 * 4;
    round_perm_kernel<<<(QLEN * DMODEL + EL4 - 1) / EL4, 256>>>(hidden, phidT, QLEN * DMODEL);
    round_kernel<<<(DMODEL * DMODEL + EL4 - 1) / EL4, 256>>>(Wq, pWqR, DMODEL * DMODEL);
    round_kernel<<<(DMODEL * KVDIM + EL4 - 1) / EL4, 256>>>(Wk, pWkR, DMODEL * KVDIM);
    round_kernel<<<(DMODEL * KVDIM + EL4 - 1) / EL4, 256>>>(Wv, pWvR, DMODEL * KVDIM);
    round_kernel<<<(DMODEL * DMODEL + EL4 - 1) / EL4, 256>>>(Wo, pWoR, DMODEL * DMODEL);

    // projections (mma.sync tf32, cp.async pipelined)
    gemm_cp<<<dim3(DMODEL / 128, QLEN / 128), 128, G_SMEM>>>(phidT, pWqR, pq, DMODEL);
    gemm_cp_kv<<<dim3(16, QLEN / 128), 128, G_SMEM>>>(phidT, pWkR, pWvR, pk, pv);

    // RoPE + cache assembly (tf32-rounded; K d-interleaved; V transposed)
    rope_q_kernel<<<(QLEN * NHEAD * 64 + 255) / 256, 256>>>();
    build_cache_kernel<<<(NKVH * KTOT * 64 + 255) / 256, 256>>>(
        sink_k, sink_v, win_k, win_v, sink_pos, key_pos);

    // attention
    attn_mma_kernel<<<dim3(NHEAD, QLEN / 128), 256, ATTN_SMEM_BYTES>>>();

    // output projection
    round_perm_kernel<<<(QLEN * DMODEL + EL4 - 1) / EL4, 256>>>(pattn, pattnT, QLEN * DMODEL);
    gemm_cp<<<dim3(DMODEL / 128, QLEN / 128), 128, G_SMEM>>>(pattnT, pWoR, out, DMODEL);
}

// round 11
// speedup vs baseline: 1.1021x; 1.1021x over previous
#include <cuda_runtime.h>
#include <cuda_bf16.h>
#include <cstdint>

// ---------------- Problem constants ----------------
#define QLEN   2048
#define DMODEL 4096
#define NHEAD  32
#define NKVH   8
#define HEADD  128
#define NSINK  4
#define NWIN   2048
#define NSNW   (NSINK + NWIN)          // 2052
#define KTOT   (NSNW + QLEN)           // 4100
#define GRP    (NHEAD / NKVH)          // 4
#define KVDIM  (NKVH * HEADD)          // 1024

#define NEG_BIG (-3.4028234663852886e38f)   // finfo(float32).min
#define LOG10000_OVER_64 0.14391156831212787f
#define ATTN_SCALE 0.08838834764831845f     // 1/sqrt(128)

// ---------------- Scratch (device globals; no runtime alloc) ----------------
__device__ float g_q[QLEN * DMODEL];        // q proj -> RoPE'd, tf32-rounded
__device__ float g_kproj[QLEN * KVDIM];
__device__ float g_vproj[QLEN * KVDIM];
__device__ float g_K[NKVH * KTOT * HEADD + 64 * HEADD];  // RoPE'd K, d-interleaved, tf32
__device__ float g_V[NKVH * KTOT * HEADD + 64 * HEADD];  // V cache, tf32
__device__ float g_attn[QLEN * DMODEL];     // attention output (pre-Wo), raw fp32
__device__ float g_bias[NSNW];              // cache bias (mask * NEG)
__device__ int   g_maxpos;

// tf32-rounded operand copies for cp.async GEMMs
__device__ float g_hidT[QLEN * DMODEL];     // hidden, rounded, perm8 k-interleaved (A op)
__device__ float g_attnT[QLEN * DMODEL];    // attn out, rounded, perm8 (A op)
__device__ float g_WqR[DMODEL * DMODEL];    // weights, rounded (B ops, layout unchanged)
__device__ float g_WkR[DMODEL * KVDIM];
__device__ float g_WvR[DMODEL * KVDIM];
__device__ float g_WoR[DMODEL * DMODEL];

__device__ __forceinline__ float neg_inf() { return __int_as_float(0xff800000u); }

// column interleave within each 8-block: pairs (c, c+4) adjacent
__device__ __forceinline__ int perm8(int d) {
    return (d & ~7) | ((d & 3) << 1) | ((d >> 2) & 1);
}

__device__ __forceinline__ uint32_t f2tf32(float x) {
    uint32_t u;
    asm("cvt.rna.tf32.f32 %0, %1;" : "=r"(u) : "f"(x));
    return u;
}
__device__ __forceinline__ float f2tf32f(float x) {
    return __uint_as_float(f2tf32(x));
}

__device__ __forceinline__ void mma_tf32(float d[4],
                                         uint32_t a0, uint32_t a1, uint32_t a2, uint32_t a3,
                                         uint32_t b0, uint32_t b1) {
    asm volatile(
        "mma.sync.aligned.m16n8k8.row.col.f32.tf32.tf32.f32 "
        "{%0,%1,%2,%3}, {%4,%5,%6,%7}, {%8,%9}, {%0,%1,%2,%3};\n"
        : "+f"(d[0]), "+f"(d[1]), "+f"(d[2]), "+f"(d[3])
        : "r"(a0), "r"(a1), "r"(a2), "r"(a3), "r"(b0), "r"(b1));
}

__device__ __forceinline__ void cp16(uint32_t dst, const float* src, bool v) {
    asm volatile("cp.async.cg.shared.global [%0], [%1], 16, %2;\n"
                 :: "r"(dst), "l"(src), "r"(v ? 16 : 0) : "memory");
}
__device__ __forceinline__ void cp_commit() {
    asm volatile("cp.async.commit_group;\n" ::: "memory");
}
__device__ __forceinline__ void cp_wait0() {
    asm volatile("cp.async.wait_group 0;\n" ::: "memory");
}
__device__ __forceinline__ void cp_wait1() {
    asm volatile("cp.async.wait_group 1;\n" ::: "memory");
}

// ---------------- max position + bias precompute ----------------
__global__ void maxpos_kernel(const int* __restrict__ sink_pos,
                              const int* __restrict__ key_pos) {
    __shared__ int sm[256];
    int tid = threadIdx.x;
    int v = -2147483647;
    for (int i = tid; i < NWIN; i += 256) v = max(v, key_pos[i]);
    for (int i = tid; i < NSINK; i += 256) v = max(v, sink_pos[i]);
    sm[tid] = v;
    __syncthreads();
    for (int s = 128; s > 0; s >>= 1) {
        if (tid < s) sm[tid] = max(sm[tid], sm[tid + s]);
        __syncthreads();
    }
    if (tid == 0) g_maxpos = sm[0] + 1;
}

__global__ void bias_kernel(const float* __restrict__ sink_mask,
                            const float* __restrict__ key_mask) {
    int i = blockIdx.x * blockDim.x + threadIdx.x;
    if (i >= NSNW) return;
    float m = (i < NSINK) ? sink_mask[i] : key_mask[i - NSINK];
    g_bias[i] = m * NEG_BIG;
}

// ---------------- prep: tf32 rounding (+ perm8 for A operands) ----------------
__global__ void round_perm_kernel(const float* __restrict__ src,
                                  float* __restrict__ dst, int n) {
    int i = (blockIdx.x * 256 + threadIdx.x) * 4;
    if (i >= n) return;
    float4 v = *(const float4*)(src + i);
    int base = i & ~7;
    if (i & 4) {            // high half of 8-block -> odd slots
        dst[base + 1] = f2tf32f(v.x);
        dst[base + 3] = f2tf32f(v.y);
        dst[base + 5] = f2tf32f(v.z);
        dst[base + 7] = f2tf32f(v.w);
    } else {                // low half -> even slots
        dst[base + 0] = f2tf32f(v.x);
        dst[base + 2] = f2tf32f(v.y);
        dst[base + 4] = f2tf32f(v.z);
        dst[base + 6] = f2tf32f(v.w);
    }
}

__global__ void round_kernel(const float* __restrict__ src,
                             float* __restrict__ dst, int n) {
    int i = (blockIdx.x * 256 + threadIdx.x) * 4;
    if (i >= n) return;
    float4 v = *(const float4*)(src + i);
    float4 o = {f2tf32f(v.x), f2tf32f(v.y), f2tf32f(v.z), f2tf32f(v.w)};
    *(float4*)(dst + i) = o;
}

// ---------------- TF32 GEMM v3: cp.async, 8 warps, 32x64 warp tile (R6 shape) ----------------
// A (pre-rounded, perm8 k-interleaved) [M][DMODEL]; B (pre-rounded) [DMODEL][N]; C[M][N].
// CTA tile 128x128, k-step 32, 2-stage cp.async double buffer, 2 CTAs/SM.
#define GA_STR 40                     // A smem row: 32 k-words + 8 pad (mod32 = 8)
#define GB_STR 136                    // B smem row: 128 n-words + 8 pad (mod32 = 8)
#define G_ABYTES (128 * GA_STR * 4)   // 20480
#define G_BBYTES (32 * GB_STR * 4)    // 17408
#define G_STAGE  (G_ABYTES + G_BBYTES)
#define G_SMEM   (2 * G_STAGE)        // 75776

__device__ __forceinline__ void g_stage_load(uint32_t sb, int t,
                                             const float* __restrict__ A,
                                             const float* __restrict__ B,
                                             int N, int cRow, int cCol, int tid) {
    uint32_t ab = sb + (t & 1) * G_STAGE;
    uint32_t bb = ab + G_ABYTES;
    const int k0 = t * 32;
    const int arow = tid >> 1, acol = (tid & 1) * 16;
    const float* ap = A + (size_t)(cRow + arow) * DMODEL + k0 + acol;
#pragma unroll
    for (int c = 0; c < 4; c++)
        cp16(ab + (arow * GA_STR + acol + c * 4) * 4, ap + c * 4, true);
    const int bk = tid >> 3, bc = (tid & 7) * 16;
    const float* bp = B + (size_t)(k0 + bk) * N + cCol + bc;
#pragma unroll
    for (int c = 0; c < 4; c++)
        cp16(bb + (bk * GB_STR + bc + c * 4) * 4, bp + c * 4, true);
}

__device__ __forceinline__ void gemm_cp_body(
    const float* __restrict__ A, const float* __restrict__ B,
    float* __restrict__ C, int N, int cRow, int cCol, char* smem) {
    const int NSTAGE = DMODEL / 32;            // 128
    const int tid  = threadIdx.x;
    const int lane = tid & 31;
    const int warp = tid >> 5;
    const int wm   = (warp >> 1) * 32;
    const int wn   = (warp & 1) * 64;
    const int r0   = lane >> 2;
    const int cq   = lane & 3;
    const uint32_t sb = (uint32_t)__cvta_generic_to_shared(smem);

    float acc[2][8][4];
#pragma unroll
    for (int mt = 0; mt < 2; mt++)
#pragma unroll
        for (int nt = 0; nt < 8; nt++)
#pragma unroll
            for (int f = 0; f < 4; f++) acc[mt][nt][f] = 0.f;

    g_stage_load(sb, 0, A, B, N, cRow, cCol, tid);
    cp_commit();

    for (int t = 0; t < NSTAGE; t++) {
        if (t + 1 < NSTAGE) {
            g_stage_load(sb, t + 1, A, B, N, cRow, cCol, tid);
            cp_commit();
            cp_wait1();
        } else {
            cp_wait0();
        }
        __syncthreads();

        const uint32_t* As = (const uint32_t*)(smem + (t & 1) * G_STAGE);
        const uint32_t* Bs = (const uint32_t*)(smem + (t & 1) * G_STAGE + G_ABYTES);
#pragma unroll
        for (int kb = 0; kb < 4; kb++) {
            const int kb8 = kb * 8;
            uint32_t a[2][4];
#pragma unroll
            for (int mt = 0; mt < 2; mt++) {
                int mr = wm + mt * 16 + r0;
                uint2 u0 = *(const uint2*)&As[mr * GA_STR + kb8 + 2 * cq];
                uint2 u1 = *(const uint2*)&As[(mr + 8) * GA_STR + kb8 + 2 * cq];
                a[mt][0] = u0.x; a[mt][1] = u1.x;
                a[mt][2] = u0.y; a[mt][3] = u1.y;
            }
#pragma unroll
            for (int nt = 0; nt < 8; nt++) {
                int nc = wn + nt * 8 + r0;
                uint32_t b0 = Bs[(kb8 + cq) * GB_STR + nc];
                uint32_t b1 = Bs[(kb8 + cq + 4) * GB_STR + nc];
                mma_tf32(acc[0][nt], a[0][0], a[0][1], a[0][2], a[0][3], b0, b1);
                mma_tf32(acc[1][nt], a[1][0], a[1][1], a[1][2], a[1][3], b0, b1);
            }
        }
        __syncthreads();
    }

#pragma unroll
    for (int mt = 0; mt < 2; mt++)
#pragma unroll
        for (int nt = 0; nt < 8; nt++) {
            int r = cRow + wm + mt * 16 + r0;
            int c = cCol + wn + nt * 8 + cq * 2;
            float2 v0 = {acc[mt][nt][0], acc[mt][nt][1]};
            float2 v1 = {acc[mt][nt][2], acc[mt][nt][3]};
            *(float2*)(C + (size_t)r * N + c)       = v0;
            *(float2*)(C + (size_t)(r + 8) * N + c) = v1;
        }
}

__global__ void __launch_bounds__(256, 2) gemm_cp(
    const float* __restrict__ A, const float* __restrict__ B,
    float* __restrict__ C, int N) {
    extern __shared__ char smg[];
    gemm_cp_body(A, B, C, N, blockIdx.y * 128, blockIdx.x * 128, smg);
}

// fused Wk|Wv projection: grid (16, 16); x<8 -> K proj, x>=8 -> V proj
__global__ void __launch_bounds__(256, 2) gemm_cp_kv(
    const float* __restrict__ A,
    const float* __restrict__ Bk, const float* __restrict__ Bv,
    float* __restrict__ Ck, float* __restrict__ Cv) {
    extern __shared__ char smg[];
    const bool isV = blockIdx.x >= 8;
    gemm_cp_body(A, isV ? Bv : Bk, isV ? Cv : Ck, KVDIM,
                 blockIdx.y * 128, (blockIdx.x & 7) * 128, smg);
}

// ---------------- RoPE on q (in place, writes tf32-rounded) ----------------
__global__ void rope_q_kernel() {
    int idx = blockIdx.x * blockDim.x + threadIdx.x;
    if (idx >= QLEN * NHEAD * 64) return;
    int i  = idx & 63;
    int hq = idx >> 6;
    int h  = hq & (NHEAD - 1);
    int t  = hq >> 5;
    float* p = g_q + (size_t)t * DMODEL + h * HEADD;
    float pos = (float)(g_maxpos + t);
    float freq = expf(-(float)i * LOG10000_OVER_64);
    float ang = pos * freq;
    float c, s;
    sincosf(ang, &s, &c);
    float x1 = p[i], x2 = p[i + 64];
    p[i]      = f2tf32f(x1 * c - x2 * s);
    p[i + 64] = f2tf32f(x2 * c + x1 * s);
}

// ---------------- Build concatenated K (RoPE'd, d-interleaved) and V caches ----------------
__global__ void build_cache_kernel(const float* __restrict__ sink_k,
                                   const float* __restrict__ sink_v,
                                   const float* __restrict__ win_k,
                                   const float* __restrict__ win_v,
                                   const int* __restrict__ sink_pos,
                                   const int* __restrict__ key_pos) {
    int idx = blockIdx.x * blockDim.x + threadIdx.x;
    if (idx >= NKVH * KTOT * 64) return;
    int i   = idx & 63;
    int rj  = idx >> 6;
    int j   = rj % KTOT;
    int kvh = rj / KTOT;

    const float* kp;
    const float* vp;
    int pos;
    if (j < NSINK) {
        kp = sink_k + (size_t)(kvh * NSINK + j) * HEADD;
        vp = sink_v + (size_t)(kvh * NSINK + j) * HEADD;
        pos = sink_pos[j];
    } else if (j < NSNW) {
        int w = j - NSINK;
        kp = win_k + (size_t)(kvh * NWIN + w) * HEADD;
        vp = win_v + (size_t)(kvh * NWIN + w) * HEADD;
        pos = key_pos[w];
    } else {
        int t = j - NSNW;
        kp = g_kproj + (size_t)t * KVDIM + kvh * HEADD;
        vp = g_vproj + (size_t)t * KVDIM + kvh * HEADD;
        pos = g_maxpos + t;
    }

    float freq = expf(-(float)i * LOG10000_OVER_64);
    float ang = (float)pos * freq;
    float c, s;
    sincosf(ang, &s, &c);
    float x1 = kp[i], x2 = kp[i + 64];

    size_t out = ((size_t)kvh * KTOT + j) * HEADD;
    g_K[out + perm8(i)]      = f2tf32f(x1 * c - x2 * s);
    g_K[out + perm8(i + 64)] = f2tf32f(x2 * c + x1 * s);
    g_V[out + i]      = f2tf32f(vp[i]);
    g_V[out + i + 64] = f2tf32f(vp[i + 64]);
}

// ---------------- Flash attention (R6, unchanged): cp.async K/V, LDS.64 frags ----------------
#define KS_STR 136
#define VS_STR 136
#define PS_STR 68
#define BUF_WORDS (64 * KS_STR + 64 * VS_STR)      // 17408
#define PS_OFF    (2 * BUF_WORDS)                   // 34816
#define ATTN_SMEM_BYTES ((PS_OFF + 128 * PS_STR) * 4)

__global__ void __launch_bounds__(256, 1) attn_mma_kernel() {
    extern __shared__ uint32_t smw[];
    const uint32_t smem_base = (uint32_t)__cvta_generic_to_shared(smw);

    const int h    = blockIdx.x;
    const int kvh  = h >> 2;                              // GRP = 4
    const int qt0  = (gridDim.y - 1 - blockIdx.y) * 128;  // long blocks first
    const int tid  = threadIdx.x;
    const int lane = tid & 31;
    const int warp = tid >> 5;
    const int qw   = warp * 16;
    const int r0   = lane >> 2;
    const int cq   = lane & 3;

    const float* Kg = g_K + (size_t)kvh * KTOT * HEADD;
    const float* Vg = g_V + (size_t)kvh * KTOT * HEADD;

    int kmax = NSNW + qt0 + 128;
    if (kmax > KTOT) kmax = KTOT;
    const int ntiles = (kmax + 63) >> 6;

    // ---- prefetch tile 0 into buf0 ----
    {
        uint32_t kbase = smem_base;
        uint32_t vbase = smem_base + 64 * KS_STR * 4;
        for (int i = tid; i < 2048; i += 256) {
            int key = i >> 5, c = i & 31;
            cp16(kbase + (key * KS_STR + c * 4) * 4, Kg + (size_t)key * HEADD + c * 4, true);
            cp16(vbase + (key * VS_STR + c * 4) * 4, Vg + (size_t)key * HEADD + c * 4, true);
        }
        cp_commit();
    }

    // ---- stage Q tile [128q][128d] into buf1 region, d-interleaved ----
    {
        uint32_t* Qs = smw + BUF_WORDS;
        const float* qg = g_q + (size_t)qt0 * DMODEL + h * HEADD;
        for (int i = tid; i < 128 * 32; i += 256) {
            int q = i >> 5, c4 = (i & 31) * 4;
            float4 v = *(const float4*)(qg + (size_t)q * DMODEL + c4);
            uint32_t* qrow = Qs + q * KS_STR;
            qrow[perm8(c4 + 0)] = __float_as_uint(v.x);
            qrow[perm8(c4 + 1)] = __float_as_uint(v.y);
            qrow[perm8(c4 + 2)] = __float_as_uint(v.z);
            qrow[perm8(c4 + 3)] = __float_as_uint(v.w);
        }
    }
    __syncthreads();

    // ---- extract Q fragments to registers (LDS.64 pairs) ----
    uint32_t QA[16][4];
    {
        const uint32_t* Qs = smw + BUF_WORDS;
#pragma unroll
        for (int kk = 0; kk < 16; kk++) {
            uint2 u0 = *(const uint2*)&Qs[(qw + r0) * KS_STR + kk * 8 + 2 * cq];
            uint2 u1 = *(const uint2*)&Qs[(qw + r0 + 8) * KS_STR + kk * 8 + 2 * cq];
            QA[kk][0] = u0.x; QA[kk][1] = u1.x;
            QA[kk][2] = u0.y; QA[kk][3] = u1.y;
        }
    }
    __syncthreads();

    float O[16][4];
#pragma unroll
    for (int nt = 0; nt < 16; nt++)
#pragma unroll
        for (int f = 0; f < 4; f++) O[nt][f] = 0.f;
    float m0 = neg_inf(), m1 = neg_inf(), l0 = 0.f, l1 = 0.f;

    const int q0 = qt0 + qw + r0;
    const int q1 = q0 + 8;

    for (int t = 0; t < ntiles; t++) {
        const int j0 = t * 64;
        const int buf = t & 1;
        const uint32_t* Ks = smw + buf * BUF_WORDS;
        const uint32_t* Vs = Ks + 64 * KS_STR;
        uint32_t* Ps = smw + PS_OFF;

        cp_wait0();
        __syncthreads();

        if (t + 1 < ntiles) {
            const int jn = j0 + 64;
            uint32_t kbase = smem_base + (buf ^ 1) * BUF_WORDS * 4;
            uint32_t vbase = kbase + 64 * KS_STR * 4;
            for (int i = tid; i < 2048; i += 256) {
                int key = i >> 5, c = i & 31;
                int j = jn + key;
                bool v = (j < KTOT);
                int jc = v ? j : (KTOT - 1);
                cp16(kbase + (key * KS_STR + c * 4) * 4, Kg + (size_t)jc * HEADD + c * 4, v);
                cp16(vbase + (key * VS_STR + c * 4) * 4, Vg + (size_t)jc * HEADD + c * 4, v);
            }
            cp_commit();
        }

        float bb[8][2];
#pragma unroll
        for (int nt = 0; nt < 8; nt++) {
            int ja = j0 + nt * 8 + cq * 2;
            bb[nt][0] = (ja < NSNW) ? g_bias[ja] : 0.f;
            bb[nt][1] = (ja + 1 < NSNW) ? g_bias[ja + 1] : 0.f;
        }

        float S[8][4];
#pragma unroll
        for (int nt = 0; nt < 8; nt++)
#pragma unroll
            for (int f = 0; f < 4; f++) S[nt][f] = 0.f;

        uint2 bc[8];
#pragma unroll
        for (int nt = 0; nt < 8; nt++)
            bc[nt] = *(const uint2*)&Ks[(nt * 8 + r0) * KS_STR + 2 * cq];

#pragma unroll
        for (int kk = 0; kk < 16; kk++) {
            uint2 bn[8];
            if (kk < 15) {
#pragma unroll
                for (int nt = 0; nt < 8; nt++)
                    bn[nt] = *(const uint2*)&Ks[(nt * 8 + r0) * KS_STR + (kk + 1) * 8 + 2 * cq];
            }
#pragma unroll
            for (int nt = 0; nt < 8; nt++)
                mma_tf32(S[nt], QA[kk][0], QA[kk][1], QA[kk][2], QA[kk][3],
                         bc[nt].x, bc[nt].y);
            if (kk < 15) {
#pragma unroll
                for (int nt = 0; nt < 8; nt++) bc[nt] = bn[nt];
            }
        }

        float rm0 = neg_inf(), rm1 = neg_inf();
#pragma unroll
        for (int nt = 0; nt < 8; nt++) {
            int ja = j0 + nt * 8 + cq * 2;
            int jb = ja + 1;
            float s0 = (ja <= q0 + NSNW) ? S[nt][0] * ATTN_SCALE + bb[nt][0] : neg_inf();
            float s1 = (jb <= q0 + NSNW) ? S[nt][1] * ATTN_SCALE + bb[nt][1] : neg_inf();
            float s2 = (ja <= q1 + NSNW) ? S[nt][2] * ATTN_SCALE + bb[nt][0] : neg_inf();
            float s3 = (jb <= q1 + NSNW) ? S[nt][3] * ATTN_SCALE + bb[nt][1] : neg_inf();
            S[nt][0] = s0; S[nt][1] = s1; S[nt][2] = s2; S[nt][3] = s3;
            rm0 = fmaxf(rm0, fmaxf(s0, s1));
            rm1 = fmaxf(rm1, fmaxf(s2, s3));
        }
        rm0 = fmaxf(rm0, __shfl_xor_sync(0xffffffffu, rm0, 1));
        rm0 = fmaxf(rm0, __shfl_xor_sync(0xffffffffu, rm0, 2));
        rm1 = fmaxf(rm1, __shfl_xor_sync(0xffffffffu, rm1, 1));
        rm1 = fmaxf(rm1, __shfl_xor_sync(0xffffffffu, rm1, 2));

        float mn0 = fmaxf(m0, rm0);
        float mn1 = fmaxf(m1, rm1);
        float mns0 = (mn0 == neg_inf()) ? 0.f : mn0;
        float mns1 = (mn1 == neg_inf()) ? 0.f : mn1;
        float f0 = __expf(m0 - mns0);
        float f1 = __expf(m1 - mns1);
        if (m0 == neg_inf()) f0 = 0.f;
        if (m1 == neg_inf()) f1 = 0.f;
        m0 = mn0; m1 = mn1;
        l0 *= f0; l1 *= f1;
#pragma unroll
        for (int nt = 0; nt < 16; nt++) {
            O[nt][0] *= f0; O[nt][1] *= f0;
            O[nt][2] *= f1; O[nt][3] *= f1;
        }

        float ps0 = 0.f, ps1 = 0.f;
#pragma unroll
        for (int nt = 0; nt < 8; nt++) {
            int col = nt * 8 + cq * 2;
            float p0 = __expf(S[nt][0] - mns0);
            float p1 = __expf(S[nt][1] - mns0);
            float p2 = __expf(S[nt][2] - mns1);
            float p3 = __expf(S[nt][3] - mns1);
            ps0 += p0 + p1;
            ps1 += p2 + p3;
            *(uint2*)&Ps[(qw + r0) * PS_STR + col]     = make_uint2(f2tf32(p0), f2tf32(p1));
            *(uint2*)&Ps[(qw + r0 + 8) * PS_STR + col] = make_uint2(f2tf32(p2), f2tf32(p3));
        }
        ps0 += __shfl_xor_sync(0xffffffffu, ps0, 1);
        ps0 += __shfl_xor_sync(0xffffffffu, ps0, 2);
        ps1 += __shfl_xor_sync(0xffffffffu, ps1, 1);
        ps1 += __shfl_xor_sync(0xffffffffu, ps1, 2);
        l0 += ps0; l1 += ps1;

        __syncwarp();

        uint32_t ac[4];
        ac[0] = Ps[(qw + r0) * PS_STR + cq];
        ac[1] = Ps[(qw + r0 + 8) * PS_STR + cq];
        ac[2] = Ps[(qw + r0) * PS_STR + cq + 4];
        ac[3] = Ps[(qw + r0 + 8) * PS_STR + cq + 4];
#pragma unroll
        for (int kk = 0; kk < 8; kk++) {
            const int kb = kk * 8;
            uint32_t an[4];
            if (kk < 7) {
                an[0] = Ps[(qw + r0) * PS_STR + kb + 8 + cq];
                an[1] = Ps[(qw + r0 + 8) * PS_STR + kb + 8 + cq];
                an[2] = Ps[(qw + r0) * PS_STR + kb + 8 + cq + 4];
                an[3] = Ps[(qw + r0 + 8) * PS_STR + kb + 8 + cq + 4];
            }
#pragma unroll
            for (int nt = 0; nt < 16; nt++) {
                uint32_t b0 = Vs[(kb + cq) * VS_STR + nt * 8 + r0];
                uint32_t b1 = Vs[(kb + cq + 4) * VS_STR + nt * 8 + r0];
                mma_tf32(O[nt], ac[0], ac[1], ac[2], ac[3], b0, b1);
            }
            if (kk < 7) {
                ac[0] = an[0]; ac[1] = an[1]; ac[2] = an[2]; ac[3] = an[3];
            }
        }
    }

    float inv0 = 1.f / l0, inv1 = 1.f / l1;
    float* og = g_attn + (size_t)h * HEADD;
#pragma unroll
    for (int nt = 0; nt < 16; nt++) {
        int c = nt * 8 + cq * 2;
        float2 v0 = {O[nt][0] * inv0, O[nt][1] * inv0};
        float2 v1 = {O[nt][2] * inv1, O[nt][3] * inv1};
        *(float2*)(og + (size_t)q0 * DMODEL + c) = v0;
        *(float2*)(og + (size_t)q1 * DMODEL + c) = v1;
    }
}

// ---------------- launch ----------------
extern "C" void kernel_launch(void* const* d_in, const int* in_sizes, int n_in,
                              void* d_out, int out_size) {
    const float* hidden    = (const float*)d_in[0];
    const float* sink_k    = (const float*)d_in[1];
    const float* sink_v    = (const float*)d_in[2];
    const float* win_k     = (const float*)d_in[3];
    const float* win_v     = (const float*)d_in[4];
    const int*   sink_pos  = (const int*)d_in[5];
    const int*   key_pos   = (const int*)d_in[6];
    const float* sink_mask = (const float*)d_in[7];
    const float* key_mask  = (const float*)d_in[8];
    const float* Wq        = (const float*)d_in[9];
    const float* Wk        = (const float*)d_in[10];
    const float* Wv        = (const float*)d_in[11];
    const float* Wo        = (const float*)d_in[12];
    float*       out       = (float*)d_out;

    float *pq, *pk, *pv, *pattn, *phidT, *pattnT, *pWqR, *pWkR, *pWvR, *pWoR;
    cudaGetSymbolAddress((void**)&pq, g_q);
    cudaGetSymbolAddress((void**)&pk, g_kproj);
    cudaGetSymbolAddress((void**)&pv, g_vproj);
    cudaGetSymbolAddress((void**)&pattn, g_attn);
    cudaGetSymbolAddress((void**)&phidT, g_hidT);
    cudaGetSymbolAddress((void**)&pattnT, g_attnT);
    cudaGetSymbolAddress((void**)&pWqR, g_WqR);
    cudaGetSymbolAddress((void**)&pWkR, g_WkR);
    cudaGetSymbolAddress((void**)&pWvR, g_WvR);
    cudaGetSymbolAddress((void**)&pWoR, g_WoR);

    static bool attr_set = false;
    if (!attr_set) {
        cudaFuncSetAttribute(attn_mma_kernel,
                             cudaFuncAttributeMaxDynamicSharedMemorySize,
                             ATTN_SMEM_BYTES);
        cudaFuncSetAttribute(gemm_cp,
                             cudaFuncAttributeMaxDynamicSharedMemorySize, G_SMEM);
        cudaFuncSetAttribute(gemm_cp_kv,
                             cudaFuncAttributeMaxDynamicSharedMemorySize, G_SMEM);
        attr_set = true;
    }

    maxpos_kernel<<<1, 256>>>(sink_pos, key_pos);
    bias_kernel<<<(NSNW + 255) / 256, 256>>>(sink_mask, key_mask);

    // prep: tf32-rounded operand copies
    const int EL4 = 256 * 4;
    round_perm_kernel<<<(QLEN * DMODEL + EL4 - 1) / EL4, 256>>>(hidden, phidT, QLEN * DMODEL);
    round_kernel<<<(DMODEL * DMODEL + EL4 - 1) / EL4, 256>>>(Wq, pWqR, DMODEL * DMODEL);
    round_kernel<<<(DMODEL * KVDIM + EL4 - 1) / EL4, 256>>>(Wk, pWkR, DMODEL * KVDIM);
    round_kernel<<<(DMODEL * KVDIM + EL4 - 1) / EL4, 256>>>(Wv, pWvR, DMODEL * KVDIM);
    round_kernel<<<(DMODEL * DMODEL + EL4 - 1) / EL4, 256>>>(Wo, pWoR, DMODEL * DMODEL);

    // projections (mma.sync tf32, cp.async 2-stage, 8 warps, 2 CTA/SM)
    gemm_cp<<<dim3(DMODEL / 128, QLEN / 128), 256, G_SMEM>>>(phidT, pWqR, pq, DMODEL);
    gemm_cp_kv<<<dim3(16, QLEN / 128), 256, G_SMEM>>>(phidT, pWkR, pWvR, pk, pv);

    // RoPE + cache assembly (tf32-rounded; K d-interleaved)
    rope_q_kernel<<<(QLEN * NHEAD * 64 + 255) / 256, 256>>>();
    build_cache_kernel<<<(NKVH * KTOT * 64 + 255) / 256, 256>>>(
        sink_k, sink_v, win_k, win_v, sink_pos, key_pos);

    // attention (R6, unchanged)
    attn_mma_kernel<<<dim3(NHEAD, QLEN / 128), 256, ATTN_SMEM_BYTES>>>();

    // output projection
    round_perm_kernel<<<(QLEN * DMODEL + EL4 - 1) / EL4, 256>>>(pattn, pattnT, QLEN * DMODEL);
    gemm_cp<<<dim3(DMODEL / 128, QLEN / 128), 256, G_SMEM>>>(pattnT, pWoR, out, DMODEL);
}

// round 14
// speedup vs baseline: 1.1343x; 1.0292x over previous
#include <cuda_runtime.h>
#include <cuda_bf16.h>
#include <cstdint>

// ---------------- Problem constants ----------------
#define QLEN   2048
#define DMODEL 4096
#define NHEAD  32
#define NKVH   8
#define HEADD  128
#define NSINK  4
#define NWIN   2048
#define NSNW   (NSINK + NWIN)          // 2052
#define KTOT   (NSNW + QLEN)           // 4100
#define GRP    (NHEAD / NKVH)          // 4
#define KVDIM  (NKVH * HEADD)          // 1024
#define VSTR   (KTOT + 64)             // 4164 (padded rows; pad stays zero)

#define NEG_BIG (-3.4028234663852886e38f)   // finfo(float32).min
#define LOG10000_OVER_64 0.14391156831212787f
#define ATTN_SCALE 0.08838834764831845f     // 1/sqrt(128)

// ---------------- Scratch (device globals; no runtime alloc) ----------------
__device__ float g_q[QLEN * DMODEL];        // q proj -> RoPE'd, tf32-rounded
__device__ float g_kproj[QLEN * KVDIM];
__device__ float g_vproj[QLEN * KVDIM];
__device__ float g_K[NKVH * KTOT * HEADD + 64 * HEADD];  // RoPE'd K, d-interleaved, tf32
__device__ float g_Vt[NKVH * HEADD * VSTR]; // V TRANSPOSED [kvh][d][key-slot], tf32; pad=0
__device__ float g_attn[QLEN * DMODEL];     // attention output (pre-Wo)
__device__ float g_bias[NSNW];              // cache bias (mask * NEG)
__device__ int   g_maxpos;

__device__ __forceinline__ float neg_inf() { return __int_as_float(0xff800000u); }

// column interleave within each 8-block: pairs (c, c+4) adjacent
__device__ __forceinline__ int perm8(int d) {
    return (d & ~7) | ((d & 3) << 1) | ((d >> 2) & 1);
}
// inverse: slot -> key within 8-block
__device__ __forceinline__ int inv8(int s) {
    return (s & ~7) | (((s & 1) << 2) | ((s >> 1) & 3));
}

__device__ __forceinline__ uint32_t f2tf32(float x) {
    uint32_t u;
    asm("cvt.rna.tf32.f32 %0, %1;" : "=r"(u) : "f"(x));
    return u;
}
__device__ __forceinline__ float f2tf32f(float x) {
    return __uint_as_float(f2tf32(x));
}

__device__ __forceinline__ void mma_tf32(float d[4],
                                         uint32_t a0, uint32_t a1, uint32_t a2, uint32_t a3,
                                         uint32_t b0, uint32_t b1) {
    asm volatile(
        "mma.sync.aligned.m16n8k8.row.col.f32.tf32.tf32.f32 "
        "{%0,%1,%2,%3}, {%4,%5,%6,%7}, {%8,%9}, {%0,%1,%2,%3};\n"
        : "+f"(d[0]), "+f"(d[1]), "+f"(d[2]), "+f"(d[3])
        : "r"(a0), "r"(a1), "r"(a2), "r"(a3), "r"(b0), "r"(b1));
}

__device__ __forceinline__ void cp16(uint32_t dst, const float* src, bool v) {
    asm volatile("cp.async.cg.shared.global [%0], [%1], 16, %2;\n"
                 :: "r"(dst), "l"(src), "r"(v ? 16 : 0) : "memory");
}
__device__ __forceinline__ void cp_commit() {
    asm volatile("cp.async.commit_group;\n" ::: "memory");
}
__device__ __forceinline__ void cp_wait0() {
    asm volatile("cp.async.wait_group 0;\n" ::: "memory");
}

// ---------------- launch 1: maxpos (block 0) + bias (blocks 1..9) ----------------
__global__ void maxbias_kernel(const int* __restrict__ sink_pos,
                               const int* __restrict__ key_pos,
                               const float* __restrict__ sink_mask,
                               const float* __restrict__ key_mask) {
    int tid = threadIdx.x;
    if (blockIdx.x == 0) {
        __shared__ int sm[256];
        int v = -2147483647;
        for (int i = tid; i < NWIN; i += 256) v = max(v, key_pos[i]);
        for (int i = tid; i < NSINK; i += 256) v = max(v, sink_pos[i]);
        sm[tid] = v;
        __syncthreads();
        for (int s = 128; s > 0; s >>= 1) {
            if (tid < s) sm[tid] = max(sm[tid], sm[tid + s]);
            __syncthreads();
        }
        if (tid == 0) g_maxpos = sm[0] + 1;
    } else {
        int i = (blockIdx.x - 1) * 256 + tid;
        if (i < NSNW) {
            float m = (i < NSINK) ? sink_mask[i] : key_mask[i - NSINK];
            g_bias[i] = m * NEG_BIG;
        }
    }
}

// ---------------- TF32 GEMM (exact R6 winner): software-pipelined ----------------
#define GSTR 136
struct GemmSmem {
    uint32_t As[32][GSTR];
    uint32_t Bs[32][GSTR];
};

__device__ __forceinline__ void gemm_body(
    const float* __restrict__ A, const float* __restrict__ B,
    float* __restrict__ C, int N, int K, int cRow, int cCol, GemmSmem& sm) {
    const int tid  = threadIdx.x;
    const int lane = tid & 31;
    const int warp = tid >> 5;
    const int wm   = (warp >> 1) * 32;
    const int wn   = (warp & 1) * 64;
    const int r0   = lane >> 2;
    const int cq   = lane & 3;

    float acc[2][8][4];
#pragma unroll
    for (int mt = 0; mt < 2; mt++)
#pragma unroll
        for (int nt = 0; nt < 8; nt++)
#pragma unroll
            for (int f = 0; f < 4; f++) acc[mt][nt][f] = 0.f;

    float4 pa[4], pb[4];

#pragma unroll
    for (int i = 0; i < 4; i++) {
        int e = (i * 256 + tid) * 4;
        int r = e >> 5, c = e & 31;
        pa[i] = *(const float4*)(A + (size_t)(cRow + r) * K + c);
        int rb = e >> 7, cb = e & 127;
        pb[i] = *(const float4*)(B + (size_t)rb * N + cCol + cb);
    }
#pragma unroll
    for (int i = 0; i < 4; i++) {
        int e = (i * 256 + tid) * 4;
        int r = e >> 5, c = e & 31;
        sm.As[c + 0][r] = f2tf32(pa[i].x);
        sm.As[c + 1][r] = f2tf32(pa[i].y);
        sm.As[c + 2][r] = f2tf32(pa[i].z);
        sm.As[c + 3][r] = f2tf32(pa[i].w);
        int rb = e >> 7, cb = e & 127;
        uint4 u = {f2tf32(pb[i].x), f2tf32(pb[i].y), f2tf32(pb[i].z), f2tf32(pb[i].w)};
        *(uint4*)&sm.Bs[rb][cb] = u;
    }
    __syncthreads();

    for (int k0 = 0; k0 < K; k0 += 32) {
        const bool more = (k0 + 32) < K;
        if (more) {
#pragma unroll
            for (int i = 0; i < 4; i++) {
                int e = (i * 256 + tid) * 4;
                int r = e >> 5, c = e & 31;
                pa[i] = *(const float4*)(A + (size_t)(cRow + r) * K + k0 + 32 + c);
                int rb = e >> 7, cb = e & 127;
                pb[i] = *(const float4*)(B + (size_t)(k0 + 32 + rb) * N + cCol + cb);
            }
        }

#pragma unroll
        for (int kk = 0; kk < 4; kk++) {
            const int kb = kk * 8;
            uint32_t af[2][4];
#pragma unroll
            for (int mt = 0; mt < 2; mt++) {
                int mr = wm + mt * 16 + r0;
                af[mt][0] = sm.As[kb + cq][mr];
                af[mt][1] = sm.As[kb + cq][mr + 8];
                af[mt][2] = sm.As[kb + 4 + cq][mr];
                af[mt][3] = sm.As[kb + 4 + cq][mr + 8];
            }
#pragma unroll
            for (int nt = 0; nt < 8; nt++) {
                int nc = wn + nt * 8 + r0;
                uint32_t b0 = sm.Bs[kb + cq][nc];
                uint32_t b1 = sm.Bs[kb + 4 + cq][nc];
                mma_tf32(acc[0][nt], af[0][0], af[0][1], af[0][2], af[0][3], b0, b1);
                mma_tf32(acc[1][nt], af[1][0], af[1][1], af[1][2], af[1][3], b0, b1);
            }
        }
        __syncthreads();

        if (more) {
#pragma unroll
            for (int i = 0; i < 4; i++) {
                int e = (i * 256 + tid) * 4;
                int r = e >> 5, c = e & 31;
                sm.As[c + 0][r] = f2tf32(pa[i].x);
                sm.As[c + 1][r] = f2tf32(pa[i].y);
                sm.As[c + 2][r] = f2tf32(pa[i].z);
                sm.As[c + 3][r] = f2tf32(pa[i].w);
                int rb = e >> 7, cb = e & 127;
                uint4 u = {f2tf32(pb[i].x), f2tf32(pb[i].y), f2tf32(pb[i].z), f2tf32(pb[i].w)};
                *(uint4*)&sm.Bs[rb][cb] = u;
            }
            __syncthreads();
        }
    }

#pragma unroll
    for (int mt = 0; mt < 2; mt++)
#pragma unroll
        for (int nt = 0; nt < 8; nt++) {
            int r = cRow + wm + mt * 16 + r0;
            int c = cCol + wn + nt * 8 + cq * 2;
            float2 v0 = {acc[mt][nt][0], acc[mt][nt][1]};
            float2 v1 = {acc[mt][nt][2], acc[mt][nt][3]};
            *(float2*)(C + (size_t)r * N + c)       = v0;
            *(float2*)(C + (size_t)(r + 8) * N + c) = v1;
        }
}

__global__ void __launch_bounds__(256) gemm_tf32(
    const float* __restrict__ A, const float* __restrict__ B,
    float* __restrict__ C, int N, int K) {
    __shared__ GemmSmem sm;
    gemm_body(A, B, C, N, K, blockIdx.y * 128, blockIdx.x * 128, sm);
}

// fused Wk|Wv projection: grid (16, 16); x<8 -> K proj, x>=8 -> V proj
__global__ void __launch_bounds__(256) gemm_tf32_kv(
    const float* __restrict__ A,
    const float* __restrict__ Bk, const float* __restrict__ Bv,
    float* __restrict__ Ck, float* __restrict__ Cv) {
    __shared__ GemmSmem sm;
    const bool isV = blockIdx.x >= 8;
    const float* B = isV ? Bv : Bk;
    float* C       = isV ? Cv : Ck;
    const int cCol = (blockIdx.x & 7) * 128;
    gemm_body(A, B, C, KVDIM, DMODEL, blockIdx.y * 128, cCol, sm);
}

// ---------------- launch 4: RoPE q (blocks < 16384) + build K (rest) ----------------
#define ROPE_BLOCKS 16384                    // QLEN*NHEAD*64 / 256
#define BUILDK_BLOCKS 8200                   // ceil(NKVH*KTOT*64 / 256)

__global__ void rope_build_kernel(const float* __restrict__ sink_k,
                                  const float* __restrict__ win_k,
                                  const int* __restrict__ sink_pos,
                                  const int* __restrict__ key_pos) {
    if (blockIdx.x < ROPE_BLOCKS) {
        int idx = blockIdx.x * 256 + threadIdx.x;
        int i  = idx & 63;
        int hq = idx >> 6;
        int h  = hq & (NHEAD - 1);
        int t  = hq >> 5;
        float* p = g_q + (size_t)t * DMODEL + h * HEADD;
        float pos = (float)(g_maxpos + t);
        float freq = expf(-(float)i * LOG10000_OVER_64);
        float ang = pos * freq;
        float c, s;
        sincosf(ang, &s, &c);
        float x1 = p[i], x2 = p[i + 64];
        p[i]      = f2tf32f(x1 * c - x2 * s);
        p[i + 64] = f2tf32f(x2 * c + x1 * s);
    } else {
        int idx = (blockIdx.x - ROPE_BLOCKS) * 256 + threadIdx.x;
        if (idx >= NKVH * KTOT * 64) return;
        int i   = idx & 63;
        int rj  = idx >> 6;
        int j   = rj % KTOT;
        int kvh = rj / KTOT;

        const float* kp;
        int pos;
        if (j < NSINK) {
            kp = sink_k + (size_t)(kvh * NSINK + j) * HEADD;
            pos = sink_pos[j];
        } else if (j < NSNW) {
            int w = j - NSINK;
            kp = win_k + (size_t)(kvh * NWIN + w) * HEADD;
            pos = key_pos[w];
        } else {
            int t = j - NSNW;
            kp = g_kproj + (size_t)t * KVDIM + kvh * HEADD;
            pos = g_maxpos + t;
        }

        float freq = expf(-(float)i * LOG10000_OVER_64);
        float ang = (float)pos * freq;
        float c, s;
        sincosf(ang, &s, &c);
        float x1 = kp[i], x2 = kp[i + 64];

        size_t out = ((size_t)kvh * KTOT + j) * HEADD;
        g_K[out + perm8(i)]      = f2tf32f(x1 * c - x2 * s);
        g_K[out + perm8(i + 64)] = f2tf32f(x2 * c + x1 * s);
    }
}

// ---------------- launch 5: V transpose (coalesced both sides) ----------------
// Block: 32 keys x 128 d for one kvh. smem tile s[32][133].
__global__ void __launch_bounds__(256) transpose_v_kernel(
    const float* __restrict__ sink_v, const float* __restrict__ win_v) {
    __shared__ float s[32][133];
    const int j0  = blockIdx.x * 32;
    const int kvh = blockIdx.y;
    const int tid = threadIdx.x;

    // phase 1: load 32 keys x 128 d, coalesced along d. warp w handles keys w, w+8, ...
    {
        const int dc = (tid & 31) * 4;       // d chunk (float4)
        const int kw = tid >> 5;             // 0..7
#pragma unroll
        for (int rep = 0; rep < 4; rep++) {
            int key = kw + rep * 8;
            int j = j0 + key;
            float4 v = make_float4(0.f, 0.f, 0.f, 0.f);
            if (j < KTOT) {
                const float* vp;
                if (j < NSINK)      vp = sink_v + (size_t)(kvh * NSINK + j) * HEADD;
                else if (j < NSNW)  vp = win_v + (size_t)(kvh * NWIN + (j - NSINK)) * HEADD;
                else                vp = g_vproj + (size_t)(j - NSNW) * KVDIM + kvh * HEADD;
                v = *(const float4*)(vp + dc);
            }
            s[key][dc + 0] = v.x;
            s[key][dc + 1] = v.y;
            s[key][dc + 2] = v.z;
            s[key][dc + 3] = v.w;
        }
    }
    __syncthreads();

    // phase 2: write g_Vt[d][slot], coalesced along slots. 32 d-rows per pass.
    {
        const int sg = (tid & 7) * 4;        // slot group base (4 slots)
#pragma unroll
        for (int pass = 0; pass < 4; pass++) {
            int d = pass * 32 + (tid >> 3);
            float4 o;
            float* po = &o.x;
#pragma unroll
            for (int u = 0; u < 4; u++) {
                int slot = sg + u;
                int key = inv8(slot);
                float val = (j0 + key < KTOT) ? f2tf32f(s[key][d]) : 0.f;
                po[u] = val;
            }
            *(float4*)(g_Vt + (size_t)(kvh * HEADD + d) * VSTR + j0 + sg) = o;
        }
    }
}

// ---------------- launch 6: Flash attention, transposed-V PV (LDS.64 frags) ----------------
// Smem word layout:
//   buf: Ks[64][136] (8704 w) + Vs[128][72] (9216 w) -> BUF_WORDS 17920
//   (Q staged at buf1 start during prologue: 17408 <= 17920)
//   Ps[128][68] @ 2*BUF_WORDS
#define KS_STR 136
#define VT_STR 72
#define PS_STR 68
#define BUF_WORDS (64 * KS_STR + 128 * VT_STR)     // 17920
#define PS_OFF    (2 * BUF_WORDS)                   // 35840
#define ATTN_SMEM_BYTES ((PS_OFF + 128 * PS_STR) * 4)

__global__ void __launch_bounds__(256, 1) attn_mma_kernel() {
    extern __shared__ uint32_t smw[];
    const uint32_t smem_base = (uint32_t)__cvta_generic_to_shared(smw);

    const int h    = blockIdx.x;
    const int kvh  = h >> 2;                              // GRP = 4
    const int qt0  = (gridDim.y - 1 - blockIdx.y) * 128;  // long blocks first
    const int tid  = threadIdx.x;
    const int lane = tid & 31;
    const int warp = tid >> 5;
    const int qw   = warp * 16;
    const int r0   = lane >> 2;
    const int cq   = lane & 3;

    const float* Kg = g_K + (size_t)kvh * KTOT * HEADD;
    const float* Vt = g_Vt + (size_t)(kvh * HEADD) * VSTR;

    int kmax = NSNW + qt0 + 128;
    if (kmax > KTOT) kmax = KTOT;
    const int ntiles = (kmax + 63) >> 6;

    // ---- prefetch tile 0 into buf0 ----
    {
        uint32_t kbase = smem_base;
        uint32_t vbase = smem_base + 64 * KS_STR * 4;
        for (int i = tid; i < 2048; i += 256) {
            int key = i >> 5, c = i & 31;
            cp16(kbase + (key * KS_STR + c * 4) * 4, Kg + (size_t)key * HEADD + c * 4, true);
        }
        for (int i = tid; i < 2048; i += 256) {
            int d = i >> 4, c = i & 15;
            cp16(vbase + (d * VT_STR + c * 4) * 4, Vt + (size_t)d * VSTR + c * 4, true);
        }
        cp_commit();
    }

    // ---- stage Q tile [128q][128d] into buf1 region, d-interleaved ----
    {
        uint32_t* Qs = smw + BUF_WORDS;
        const float* qg = g_q + (size_t)qt0 * DMODEL + h * HEADD;
        for (int i = tid; i < 128 * 32; i += 256) {
            int q = i >> 5, c4 = (i & 31) * 4;
            float4 v = *(const float4*)(qg + (size_t)q * DMODEL + c4);
            uint32_t* qrow = Qs + q * KS_STR;
            qrow[perm8(c4 + 0)] = __float_as_uint(v.x);
            qrow[perm8(c4 + 1)] = __float_as_uint(v.y);
            qrow[perm8(c4 + 2)] = __float_as_uint(v.z);
            qrow[perm8(c4 + 3)] = __float_as_uint(v.w);
        }
    }
    __syncthreads();

    // ---- extract Q fragments to registers (LDS.64 pairs) ----
    uint32_t QA[16][4];
    {
        const uint32_t* Qs = smw + BUF_WORDS;
#pragma unroll
        for (int kk = 0; kk < 16; kk++) {
            uint2 u0 = *(const uint2*)&Qs[(qw + r0) * KS_STR + kk * 8 + 2 * cq];
            uint2 u1 = *(const uint2*)&Qs[(qw + r0 + 8) * KS_STR + kk * 8 + 2 * cq];
            QA[kk][0] = u0.x; QA[kk][1] = u1.x;
            QA[kk][2] = u0.y; QA[kk][3] = u1.y;
        }
    }
    __syncthreads();

    float O[16][4];
#pragma unroll
    for (int nt = 0; nt < 16; nt++)
#pragma unroll
        for (int f = 0; f < 4; f++) O[nt][f] = 0.f;
    float m0 = neg_inf(), m1 = neg_inf(), l0 = 0.f, l1 = 0.f;

    const int q0 = qt0 + qw + r0;
    const int q1 = q0 + 8;

    for (int t = 0; t < ntiles; t++) {
        const int j0 = t * 64;
        const int buf = t & 1;
        const uint32_t* Ks = smw + buf * BUF_WORDS;
        const uint32_t* Vs = Ks + 64 * KS_STR;
        uint32_t* Ps = smw + PS_OFF;

        cp_wait0();
        __syncthreads();

        if (t + 1 < ntiles) {
            const int jn = j0 + 64;
            uint32_t kbase = smem_base + (buf ^ 1) * BUF_WORDS * 4;
            uint32_t vbase = kbase + 64 * KS_STR * 4;
            for (int i = tid; i < 2048; i += 256) {
                int key = i >> 5, c = i & 31;
                int j = jn + key;
                bool v = (j < KTOT);
                int jc = v ? j : (KTOT - 1);
                cp16(kbase + (key * KS_STR + c * 4) * 4, Kg + (size_t)jc * HEADD + c * 4, v);
            }
            for (int i = tid; i < 2048; i += 256) {
                int d = i >> 4, c = i & 15;
                // Vt rows are VSTR wide (zero pad past KTOT) -> always in-bounds
                cp16(vbase + (d * VT_STR + c * 4) * 4, Vt + (size_t)d * VSTR + jn + c * 4, true);
            }
            cp_commit();
        }

        float bb[8][2];
#pragma unroll
        for (int nt = 0; nt < 8; nt++) {
            int ja = j0 + nt * 8 + cq * 2;
            bb[nt][0] = (ja < NSNW) ? g_bias[ja] : 0.f;
            bb[nt][1] = (ja + 1 < NSNW) ? g_bias[ja + 1] : 0.f;
        }

        // ---- S = Q @ K^T ----
        float S[8][4];
#pragma unroll
        for (int nt = 0; nt < 8; nt++)
#pragma unroll
            for (int f = 0; f < 4; f++) S[nt][f] = 0.f;

        uint2 bc[8];
#pragma unroll
        for (int nt = 0; nt < 8; nt++)
            bc[nt] = *(const uint2*)&Ks[(nt * 8 + r0) * KS_STR + 2 * cq];

#pragma unroll
        for (int kk = 0; kk < 16; kk++) {
            uint2 bn[8];
            if (kk < 15) {
#pragma unroll
                for (int nt = 0; nt < 8; nt++)
                    bn[nt] = *(const uint2*)&Ks[(nt * 8 + r0) * KS_STR + (kk + 1) * 8 + 2 * cq];
            }
#pragma unroll
            for (int nt = 0; nt < 8; nt++)
                mma_tf32(S[nt], QA[kk][0], QA[kk][1], QA[kk][2], QA[kk][3],
                         bc[nt].x, bc[nt].y);
            if (kk < 15) {
#pragma unroll
                for (int nt = 0; nt < 8; nt++) bc[nt] = bn[nt];
            }
        }

        // ---- online softmax ----
        float rm0 = neg_inf(), rm1 = neg_inf();
#pragma unroll
        for (int nt = 0; nt < 8; nt++) {
            int ja = j0 + nt * 8 + cq * 2;
            int jb = ja + 1;
            float s0 = (ja <= q0 + NSNW) ? S[nt][0] * ATTN_SCALE + bb[nt][0] : neg_inf();
            float s1 = (jb <= q0 + NSNW) ? S[nt][1] * ATTN_SCALE + bb[nt][1] : neg_inf();
            float s2 = (ja <= q1 + NSNW) ? S[nt][2] * ATTN_SCALE + bb[nt][0] : neg_inf();
            float s3 = (jb <= q1 + NSNW) ? S[nt][3] * ATTN_SCALE + bb[nt][1] : neg_inf();
            S[nt][0] = s0; S[nt][1] = s1; S[nt][2] = s2; S[nt][3] = s3;
            rm0 = fmaxf(rm0, fmaxf(s0, s1));
            rm1 = fmaxf(rm1, fmaxf(s2, s3));
        }
        rm0 = fmaxf(rm0, __shfl_xor_sync(0xffffffffu, rm0, 1));
        rm0 = fmaxf(rm0, __shfl_xor_sync(0xffffffffu, rm0, 2));
        rm1 = fmaxf(rm1, __shfl_xor_sync(0xffffffffu, rm1, 1));
        rm1 = fmaxf(rm1, __shfl_xor_sync(0xffffffffu, rm1, 2));

        float mn0 = fmaxf(m0, rm0);
        float mn1 = fmaxf(m1, rm1);
        float mns0 = (mn0 == neg_inf()) ? 0.f : mn0;
        float mns1 = (mn1 == neg_inf()) ? 0.f : mn1;
        float f0 = __expf(m0 - mns0);
        float f1 = __expf(m1 - mns1);
        if (m0 == neg_inf()) f0 = 0.f;
        if (m1 == neg_inf()) f1 = 0.f;
        m0 = mn0; m1 = mn1;
        l0 *= f0; l1 *= f1;
#pragma unroll
        for (int nt = 0; nt < 16; nt++) {
            O[nt][0] *= f0; O[nt][1] *= f0;
            O[nt][2] *= f1; O[nt][3] *= f1;
        }

        float ps0 = 0.f, ps1 = 0.f;
#pragma unroll
        for (int nt = 0; nt < 8; nt++) {
            int col = nt * 8 + cq * 2;
            float p0 = __expf(S[nt][0] - mns0);
            float p1 = __expf(S[nt][1] - mns0);
            float p2 = __expf(S[nt][2] - mns1);
            float p3 = __expf(S[nt][3] - mns1);
            ps0 += p0 + p1;
            ps1 += p2 + p3;
            *(uint2*)&Ps[(qw + r0) * PS_STR + col]     = make_uint2(f2tf32(p0), f2tf32(p1));
            *(uint2*)&Ps[(qw + r0 + 8) * PS_STR + col] = make_uint2(f2tf32(p2), f2tf32(p3));
        }
        ps0 += __shfl_xor_sync(0xffffffffu, ps0, 1);
        ps0 += __shfl_xor_sync(0xffffffffu, ps0, 2);
        ps1 += __shfl_xor_sync(0xffffffffu, ps1, 1);
        ps1 += __shfl_xor_sync(0xffffffffu, ps1, 2);
        l0 += ps0; l1 += ps1;

        __syncwarp();

        // ---- O += P @ V (Vs is [d][key-slot]; B-frags are LDS.64) ----
        uint32_t ac[4];
        ac[0] = Ps[(qw + r0) * PS_STR + cq];
        ac[1] = Ps[(qw + r0 + 8) * PS_STR + cq];
        ac[2] = Ps[(qw + r0) * PS_STR + cq + 4];
        ac[3] = Ps[(qw + r0 + 8) * PS_STR + cq + 4];
#pragma unroll
        for (int kk = 0; kk < 8; kk++) {
            const int kb = kk * 8;
            uint32_t an[4];
            if (kk < 7) {
                an[0] = Ps[(qw + r0) * PS_STR + kb + 8 + cq];
                an[1] = Ps[(qw + r0 + 8) * PS_STR + kb + 8 + cq];
                an[2] = Ps[(qw + r0) * PS_STR + kb + 8 + cq + 4];
                an[3] = Ps[(qw + r0 + 8) * PS_STR + kb + 8 + cq + 4];
            }
#pragma unroll
            for (int nt = 0; nt < 16; nt++) {
                uint2 vv = *(const uint2*)&Vs[(nt * 8 + r0) * VT_STR + kb + 2 * cq];
                mma_tf32(O[nt], ac[0], ac[1], ac[2], ac[3], vv.x, vv.y);
            }
            if (kk < 7) {
                ac[0] = an[0]; ac[1] = an[1]; ac[2] = an[2]; ac[3] = an[3];
            }
        }
    }

    float inv0 = 1.f / l0, inv1 = 1.f / l1;
    float* og = g_attn + (size_t)h * HEADD;
#pragma unroll
    for (int nt = 0; nt < 16; nt++) {
        int c = nt * 8 + cq * 2;
        float2 v0 = {O[nt][0] * inv0, O[nt][1] * inv0};
        float2 v1 = {O[nt][2] * inv1, O[nt][3] * inv1};
        *(float2*)(og + (size_t)q0 * DMODEL + c) = v0;
        *(float2*)(og + (size_t)q1 * DMODEL + c) = v1;
    }
}

// ---------------- launch ----------------
extern "C" void kernel_launch(void* const* d_in, const int* in_sizes, int n_in,
                              void* d_out, int out_size) {
    const float* hidden    = (const float*)d_in[0];
    const float* sink_k    = (const float*)d_in[1];
    const float* sink_v    = (const float*)d_in[2];
    const float* win_k     = (const float*)d_in[3];
    const float* win_v     = (const float*)d_in[4];
    const int*   sink_pos  = (const int*)d_in[5];
    const int*   key_pos   = (const int*)d_in[6];
    const float* sink_mask = (const float*)d_in[7];
    const float* key_mask  = (const float*)d_in[8];
    const float* Wq        = (const float*)d_in[9];
    const float* Wk        = (const float*)d_in[10];
    const float* Wv        = (const float*)d_in[11];
    const float* Wo        = (const float*)d_in[12];
    float*       out       = (float*)d_out;

    float *pq, *pk, *pv, *pattn;
    cudaGetSymbolAddress((void**)&pq, g_q);
    cudaGetSymbolAddress((void**)&pk, g_kproj);
    cudaGetSymbolAddress((void**)&pv, g_vproj);
    cudaGetSymbolAddress((void**)&pattn, g_attn);

    static bool attr_set = false;
    if (!attr_set) {
        cudaFuncSetAttribute(attn_mma_kernel,
                             cudaFuncAttributeMaxDynamicSharedMemorySize,
                             ATTN_SMEM_BYTES);
        attr_set = true;
    }

    // launch 1: maxpos + bias
    maxbias_kernel<<<1 + (NSNW + 255) / 256, 256>>>(sink_pos, key_pos, sink_mask, key_mask);

    // launches 2-3: projections (tf32 mma, R6 pipelined)
    gemm_tf32<<<dim3(DMODEL / 128, QLEN / 128), 256>>>(hidden, Wq, pq, DMODEL, DMODEL);
    gemm_tf32_kv<<<dim3(16, QLEN / 128), 256>>>(hidden, Wk, Wv, pk, pv);

    // launch 4: RoPE q + build K (fused)
    rope_build_kernel<<<ROPE_BLOCKS + BUILDK_BLOCKS, 256>>>(sink_k, win_k, sink_pos, key_pos);

    // launch 5: V transpose into g_Vt
    transpose_v_kernel<<<dim3((KTOT + 31) / 32, NKVH), 256>>>(sink_v, win_v);

    // launch 6: attention (ncu -s 5 -c 1 captures this one)
    attn_mma_kernel<<<dim3(NHEAD, QLEN / 128), 256, ATTN_SMEM_BYTES>>>();

    // launch 7: output projection
    gemm_tf32<<<dim3(DMODEL / 128, QLEN / 128), 256>>>(pattn, Wo, out, DMODEL, DMODEL);
}

// round 17
// speedup vs baseline: 2.3788x; 2.0972x over previous
#include <cuda_runtime.h>
#include <cuda_fp16.h>
#include <cstdint>

// ---------------- Problem constants ----------------
#define QLEN   2048
#define DMODEL 4096
#define NHEAD  32
#define NKVH   8
#define HEADD  128
#define NSINK  4
#define NWIN   2048
#define NSNW   (NSINK + NWIN)          // 2052
#define KTOT   (NSNW + QLEN)           // 4100
#define GRP    (NHEAD / NKVH)          // 4
#define KVDIM  (NKVH * HEADD)          // 1024
// Vt row stride in halves. MUST be a multiple of 8 halves (16 bytes) so every
// row base is 16B-aligned for cp.async.cg 16 (R14 bug: 4164 -> odd rows 8B-aligned).
#define VSTR   4168

#define NEG_BIG (-3.4028234663852886e38f)
#define LOG10000_OVER_64 0.14391156831212787f
#define ATTN_SCALE 0.08838834764831845f     // 1/sqrt(128)

// ---------------- Scratch (device globals; no runtime alloc) ----------------
__device__ float  g_q[QLEN * DMODEL];        // Wq output (f32)
__device__ float  g_kproj[QLEN * KVDIM];
__device__ float  g_vproj[QLEN * KVDIM];
__device__ __half g_hidH[QLEN * DMODEL];     // hidden, fp16 [m][k]
__device__ __half g_WqT[(size_t)DMODEL * DMODEL];  // weights fp16, TRANSPOSED [n][k]
__device__ __half g_WkT[(size_t)KVDIM * DMODEL];
__device__ __half g_WvT[(size_t)KVDIM * DMODEL];
__device__ __half g_WoT[(size_t)DMODEL * DMODEL];
__device__ __half g_qH[QLEN * DMODEL];       // RoPE'd q, fp16
__device__ __half g_KH[NKVH * KTOT * HEADD + 64 * HEADD];  // RoPE'd K, fp16, [kvh][j][d]
__device__ __half g_VtH[NKVH * HEADD * VSTR];              // V fp16 TRANSPOSED [kvh][d][key]; pad=0
__device__ __half g_attnH[QLEN * DMODEL];    // attention out, fp16 [m][k]
__device__ float  g_bias[NSNW];
__device__ int    g_maxpos;

__device__ __forceinline__ float neg_inf() { return __int_as_float(0xff800000u); }

__device__ __forceinline__ uint32_t f2h2(float lo, float hi) {
    __half2 h = __floats2half2_rn(lo, hi);
    return *reinterpret_cast<uint32_t*>(&h);
}

__device__ __forceinline__ void mma_f16(float d[4],
                                        uint32_t a0, uint32_t a1, uint32_t a2, uint32_t a3,
                                        uint32_t b0, uint32_t b1) {
    asm volatile(
        "mma.sync.aligned.m16n8k16.row.col.f32.f16.f16.f32 "
        "{%0,%1,%2,%3}, {%4,%5,%6,%7}, {%8,%9}, {%0,%1,%2,%3};\n"
        : "+f"(d[0]), "+f"(d[1]), "+f"(d[2]), "+f"(d[3])
        : "r"(a0), "r"(a1), "r"(a2), "r"(a3), "r"(b0), "r"(b1));
}

__device__ __forceinline__ void cp16(uint32_t dst, const void* src, bool v) {
    asm volatile("cp.async.cg.shared.global [%0], [%1], 16, %2;\n"
                 :: "r"(dst), "l"(src), "r"(v ? 16 : 0) : "memory");
}
__device__ __forceinline__ void cp_commit() {
    asm volatile("cp.async.commit_group;\n" ::: "memory");
}
__device__ __forceinline__ void cp_wait0() {
    asm volatile("cp.async.wait_group 0;\n" ::: "memory");
}
__device__ __forceinline__ void cp_wait1() {
    asm volatile("cp.async.wait_group 1;\n" ::: "memory");
}

// ---------------- maxpos + bias ----------------
__global__ void maxbias_kernel(const int* __restrict__ sink_pos,
                               const int* __restrict__ key_pos,
                               const float* __restrict__ sink_mask,
                               const float* __restrict__ key_mask) {
    int tid = threadIdx.x;
    if (blockIdx.x == 0) {
        __shared__ int sm[256];
        int v = -2147483647;
        for (int i = tid; i < NWIN; i += 256) v = max(v, key_pos[i]);
        for (int i = tid; i < NSINK; i += 256) v = max(v, sink_pos[i]);
        sm[tid] = v;
        __syncthreads();
        for (int s = 128; s > 0; s >>= 1) {
            if (tid < s) sm[tid] = max(sm[tid], sm[tid + s]);
            __syncthreads();
        }
        if (tid == 0) g_maxpos = sm[0] + 1;
    } else {
        int i = (blockIdx.x - 1) * 256 + tid;
        if (i < NSNW) {
            float m = (i < NSINK) ? sink_mask[i] : key_mask[i - NSINK];
            g_bias[i] = m * NEG_BIG;
        }
    }
}

// ---------------- prep: f32 -> fp16 straight copy ----------------
__global__ void h2h_kernel(const float* __restrict__ src, __half* __restrict__ dst, int n) {
    int i = (blockIdx.x * 256 + threadIdx.x) * 8;
    if (i >= n) return;
    float4 a = *(const float4*)(src + i);
    float4 b = *(const float4*)(src + i + 4);
    uint4 o = {f2h2(a.x, a.y), f2h2(a.z, a.w), f2h2(b.x, b.y), f2h2(b.z, b.w)};
    *(uint4*)(dst + i) = o;
}

// ---------------- prep: W [K][N] f32 -> Wt [N][K] fp16 (32x32 smem tiles) ----------------
__global__ void wtrans_kernel(const float* __restrict__ W, __half* __restrict__ Wt, int Ndim) {
    __shared__ float s[32][33];
    const int k0 = blockIdx.y * 32, n0 = blockIdx.x * 32;
    const int tid = threadIdx.x;
    {
        int kk = tid >> 3, nn = (tid & 7) * 4;
        float4 v = *(const float4*)(W + (size_t)(k0 + kk) * Ndim + n0 + nn);
        s[kk][nn] = v.x; s[kk][nn + 1] = v.y; s[kk][nn + 2] = v.z; s[kk][nn + 3] = v.w;
    }
    __syncthreads();
    {
        int nn = tid >> 3, kk = (tid & 7) * 4;
        uint2 o = {f2h2(s[kk][nn], s[kk + 1][nn]), f2h2(s[kk + 2][nn], s[kk + 3][nn])};
        *(uint2*)(Wt + (size_t)(n0 + nn) * DMODEL + k0 + kk) = o;
    }
}

// ---------------- FP16 GEMM: C[M][N] f32 = A[M][K]h @ Bt[N][K]h^T ----------------
// CTA 128x128, k-step 32 (2 x k16 mma), 8 warps (4x2, warp tile 32x64), 2 CTA/SM.
#define GH_STR 20                        // smem row: 16 half2-words + 4 pad
#define GH_HALF 2560                     // words per operand tile: 128*20
#define GH_STAGE (2 * GH_HALF)           // 5120 words per stage (A+B)

__device__ __forceinline__ void gh_load(uint32_t sb, int t,
                                        const __half* __restrict__ A,
                                        const __half* __restrict__ Bt,
                                        int cRow, int cCol, int tid) {
    uint32_t base = sb + ((t & 1) * GH_STAGE) * 4;
    const int k0 = t * 32;
#pragma unroll
    for (int i = 0; i < 2; i++) {
        int c = tid + 256 * i;
        int row = c >> 2, ch = c & 3;
        cp16(base + (row * GH_STR + ch * 4) * 4,
             A + (size_t)(cRow + row) * DMODEL + k0 + ch * 8, true);
    }
#pragma unroll
    for (int i = 0; i < 2; i++) {
        int c = tid + 256 * i;
        int row = c >> 2, ch = c & 3;
        cp16(base + (GH_HALF + row * GH_STR + ch * 4) * 4,
             Bt + (size_t)(cCol + row) * DMODEL + k0 + ch * 8, true);
    }
}

__device__ __forceinline__ void gemm_f16_body(
    const __half* __restrict__ A, const __half* __restrict__ Bt,
    float* __restrict__ C, int N, int cRow, int cCol, uint32_t* sm) {
    const int NST = DMODEL / 32;               // 128
    const int tid  = threadIdx.x;
    const int lane = tid & 31;
    const int warp = tid >> 5;
    const int wm   = (warp >> 1) * 32;
    const int wn   = (warp & 1) * 64;
    const int r0   = lane >> 2;
    const int cq   = lane & 3;
    const uint32_t sb = (uint32_t)__cvta_generic_to_shared(sm);

    float acc[2][8][4];
#pragma unroll
    for (int mt = 0; mt < 2; mt++)
#pragma unroll
        for (int nt = 0; nt < 8; nt++)
#pragma unroll
            for (int f = 0; f < 4; f++) acc[mt][nt][f] = 0.f;

    gh_load(sb, 0, A, Bt, cRow, cCol, tid);
    cp_commit();

    for (int t = 0; t < NST; t++) {
        if (t + 1 < NST) {
            gh_load(sb, t + 1, A, Bt, cRow, cCol, tid);
            cp_commit();
            cp_wait1();
        } else {
            cp_wait0();
        }
        __syncthreads();

        const uint32_t* As = sm + (t & 1) * GH_STAGE;
        const uint32_t* Bs = As + GH_HALF;
#pragma unroll
        for (int s = 0; s < 2; s++) {
            const int kw = s * 8;
            uint32_t a[2][4];
#pragma unroll
            for (int mt = 0; mt < 2; mt++) {
                int mr = wm + mt * 16 + r0;
                a[mt][0] = As[mr * GH_STR + kw + cq];
                a[mt][1] = As[(mr + 8) * GH_STR + kw + cq];
                a[mt][2] = As[mr * GH_STR + kw + cq + 4];
                a[mt][3] = As[(mr + 8) * GH_STR + kw + cq + 4];
            }
#pragma unroll
            for (int nt = 0; nt < 8; nt++) {
                int nc = wn + nt * 8 + r0;
                uint32_t b0 = Bs[nc * GH_STR + kw + cq];
                uint32_t b1 = Bs[nc * GH_STR + kw + cq + 4];
                mma_f16(acc[0][nt], a[0][0], a[0][1], a[0][2], a[0][3], b0, b1);
                mma_f16(acc[1][nt], a[1][0], a[1][1], a[1][2], a[1][3], b0, b1);
            }
        }
        __syncthreads();
    }

#pragma unroll
    for (int mt = 0; mt < 2; mt++)
#pragma unroll
        for (int nt = 0; nt < 8; nt++) {
            int r = cRow + wm + mt * 16 + r0;
            int c = cCol + wn + nt * 8 + cq * 2;
            float2 v0 = {acc[mt][nt][0], acc[mt][nt][1]};
            float2 v1 = {acc[mt][nt][2], acc[mt][nt][3]};
            *(float2*)(C + (size_t)r * N + c)       = v0;
            *(float2*)(C + (size_t)(r + 8) * N + c) = v1;
        }
}

__global__ void __launch_bounds__(256, 2) gemm_f16(
    const __half* __restrict__ A, const __half* __restrict__ Bt,
    float* __restrict__ C, int N) {
    __shared__ uint32_t sm[2 * GH_STAGE];
    gemm_f16_body(A, Bt, C, N, blockIdx.y * 128, blockIdx.x * 128, sm);
}

__global__ void __launch_bounds__(256, 2) gemm_f16_kv(const __half* __restrict__ A) {
    __shared__ uint32_t sm[2 * GH_STAGE];
    const bool isV = blockIdx.x >= 8;
    gemm_f16_body(A, isV ? g_WvT : g_WkT, isV ? g_vproj : g_kproj, KVDIM,
                  blockIdx.y * 128, (blockIdx.x & 7) * 128, sm);
}

// ---------------- RoPE q -> g_qH (fp16) + build K -> g_KH (fp16) ----------------
#define ROPE_BLOCKS 16384
#define BUILDK_BLOCKS 8200

__global__ void rope_build_kernel(const float* __restrict__ sink_k,
                                  const float* __restrict__ win_k,
                                  const int* __restrict__ sink_pos,
                                  const int* __restrict__ key_pos) {
    if (blockIdx.x < ROPE_BLOCKS) {
        int idx = blockIdx.x * 256 + threadIdx.x;
        int i  = idx & 63;
        int hq = idx >> 6;
        int h  = hq & (NHEAD - 1);
        int t  = hq >> 5;
        const float* p = g_q + (size_t)t * DMODEL + h * HEADD;
        float pos = (float)(g_maxpos + t);
        float freq = expf(-(float)i * LOG10000_OVER_64);
        float ang = pos * freq;
        float c, s;
        sincosf(ang, &s, &c);
        float x1 = p[i], x2 = p[i + 64];
        __half* o = g_qH + (size_t)t * DMODEL + h * HEADD;
        o[i]      = __float2half_rn(x1 * c - x2 * s);
        o[i + 64] = __float2half_rn(x2 * c + x1 * s);
    } else {
        int idx = (blockIdx.x - ROPE_BLOCKS) * 256 + threadIdx.x;
        if (idx >= NKVH * KTOT * 64) return;
        int i   = idx & 63;
        int rj  = idx >> 6;
        int j   = rj % KTOT;
        int kvh = rj / KTOT;

        const float* kp;
        int pos;
        if (j < NSINK) {
            kp = sink_k + (size_t)(kvh * NSINK + j) * HEADD;
            pos = sink_pos[j];
        } else if (j < NSNW) {
            int w = j - NSINK;
            kp = win_k + (size_t)(kvh * NWIN + w) * HEADD;
            pos = key_pos[w];
        } else {
            int t = j - NSNW;
            kp = g_kproj + (size_t)t * KVDIM + kvh * HEADD;
            pos = g_maxpos + t;
        }

        float freq = expf(-(float)i * LOG10000_OVER_64);
        float ang = (float)pos * freq;
        float c, s;
        sincosf(ang, &s, &c);
        float x1 = kp[i], x2 = kp[i + 64];

        __half* o = g_KH + ((size_t)kvh * KTOT + j) * HEADD;
        o[i]      = __float2half_rn(x1 * c - x2 * s);
        o[i + 64] = __float2half_rn(x2 * c + x1 * s);
    }
}

// ---------------- V transpose -> g_VtH (fp16, [d][key], coalesced) ----------------
__global__ void __launch_bounds__(256) transpose_v_kernel(
    const float* __restrict__ sink_v, const float* __restrict__ win_v) {
    __shared__ float s[32][133];
    const int j0  = blockIdx.x * 32;
    const int kvh = blockIdx.y;
    const int tid = threadIdx.x;

    {
        const int dc = (tid & 31) * 4;
        const int kw = tid >> 5;
#pragma unroll
        for (int rep = 0; rep < 4; rep++) {
            int key = kw + rep * 8;
            int j = j0 + key;
            float4 v = make_float4(0.f, 0.f, 0.f, 0.f);
            if (j < KTOT) {
                const float* vp;
                if (j < NSINK)      vp = sink_v + (size_t)(kvh * NSINK + j) * HEADD;
                else if (j < NSNW)  vp = win_v + (size_t)(kvh * NWIN + (j - NSINK)) * HEADD;
                else                vp = g_vproj + (size_t)(j - NSNW) * KVDIM + kvh * HEADD;
                v = *(const float4*)(vp + dc);
            }
            s[key][dc + 0] = v.x;
            s[key][dc + 1] = v.y;
            s[key][dc + 2] = v.z;
            s[key][dc + 3] = v.w;
        }
    }
    __syncthreads();

    {
        const int kg = (tid & 7) * 4;        // key group (4 keys)
#pragma unroll
        for (int pass = 0; pass < 4; pass++) {
            int d = pass * 32 + (tid >> 3);
            float v0 = (j0 + kg + 0 < KTOT) ? s[kg + 0][d] : 0.f;
            float v1 = (j0 + kg + 1 < KTOT) ? s[kg + 1][d] : 0.f;
            float v2 = (j0 + kg + 2 < KTOT) ? s[kg + 2][d] : 0.f;
            float v3 = (j0 + kg + 3 < KTOT) ? s[kg + 3][d] : 0.f;
            uint2 o = {f2h2(v0, v1), f2h2(v2, v3)};
            *(uint2*)(g_VtH + (size_t)(kvh * HEADD + d) * VSTR + j0 + kg) = o;
        }
    }
}

// ---------------- Flash attention (fp16 mma m16n8k16) ----------------
// smem words: Ks[64][68] (4352) + Vs[128][36] (4608) per buf -> 8960; x2 = 17920
// Q staged in buf1 region during prologue (8704 <= 8960). Ps[128][36] @ 17920.
#define KSW 68
#define VSW 36
#define PSW 36
#define ABUF_W (64 * KSW + 128 * VSW)       // 8960
#define APS_OFF (2 * ABUF_W)                 // 17920
#define ATTN_SMEM_BYTES ((APS_OFF + 128 * PSW) * 4)   // 90112

__global__ void __launch_bounds__(256, 1) attn_mma_kernel() {
    extern __shared__ uint32_t smw[];
    const uint32_t smem_base = (uint32_t)__cvta_generic_to_shared(smw);

    const int h    = blockIdx.x;
    const int kvh  = h >> 2;
    const int qt0  = (gridDim.y - 1 - blockIdx.y) * 128;
    const int tid  = threadIdx.x;
    const int lane = tid & 31;
    const int warp = tid >> 5;
    const int qw   = warp * 16;
    const int r0   = lane >> 2;
    const int cq   = lane & 3;

    const __half* Kg = g_KH + (size_t)kvh * KTOT * HEADD;
    const __half* Vt = g_VtH + (size_t)(kvh * HEADD) * VSTR;

    int kmax = NSNW + qt0 + 128;
    if (kmax > KTOT) kmax = KTOT;
    const int ntiles = (kmax + 63) >> 6;

    // ---- prefetch tile 0 into buf0 ----
    {
        uint32_t kbase = smem_base;
        uint32_t vbase = smem_base + 64 * KSW * 4;
        for (int i = tid; i < 1024; i += 256) {
            int key = i >> 4, c = i & 15;
            cp16(kbase + (key * KSW + c * 4) * 4, Kg + (size_t)key * HEADD + c * 8, true);
        }
        for (int i = tid; i < 1024; i += 256) {
            int d = i >> 3, c = i & 7;
            cp16(vbase + (d * VSW + c * 4) * 4, Vt + (size_t)d * VSTR + c * 8, true);
        }
        cp_commit();
    }

    // ---- stage Q tile [128q][128d] (fp16) into buf1 region ----
    {
        uint32_t* Qs = smw + ABUF_W;
        const __half* qg = g_qH + (size_t)qt0 * DMODEL + h * HEADD;
        for (int i = tid; i < 2048; i += 256) {
            int q = i >> 4, c4 = (i & 15) * 4;     // word offset
            uint4 v = *(const uint4*)(qg + (size_t)q * DMODEL + c4 * 2);
            *(uint4*)&Qs[q * KSW + c4] = v;
        }
    }
    __syncthreads();

    // ---- Q fragments: 8 k16-steps x 4 regs ----
    uint32_t QA[8][4];
    {
        const uint32_t* Qs = smw + ABUF_W;
#pragma unroll
        for (int s = 0; s < 8; s++) {
            QA[s][0] = Qs[(qw + r0) * KSW + s * 8 + cq];
            QA[s][1] = Qs[(qw + r0 + 8) * KSW + s * 8 + cq];
            QA[s][2] = Qs[(qw + r0) * KSW + s * 8 + cq + 4];
            QA[s][3] = Qs[(qw + r0 + 8) * KSW + s * 8 + cq + 4];
        }
    }
    __syncthreads();

    float O[16][4];
#pragma unroll
    for (int nt = 0; nt < 16; nt++)
#pragma unroll
        for (int f = 0; f < 4; f++) O[nt][f] = 0.f;
    float m0 = neg_inf(), m1 = neg_inf(), l0 = 0.f, l1 = 0.f;

    const int q0 = qt0 + qw + r0;
    const int q1 = q0 + 8;

    for (int t = 0; t < ntiles; t++) {
        const int j0 = t * 64;
        const int buf = t & 1;
        const uint32_t* Ks = smw + buf * ABUF_W;
        const uint32_t* Vs = Ks + 64 * KSW;
        uint32_t* Ps = smw + APS_OFF;

        cp_wait0();
        __syncthreads();

        if (t + 1 < ntiles) {
            const int jn = j0 + 64;
            uint32_t kbase = smem_base + (buf ^ 1) * ABUF_W * 4;
            uint32_t vbase = kbase + 64 * KSW * 4;
            for (int i = tid; i < 1024; i += 256) {
                int key = i >> 4, c = i & 15;
                int j = jn + key;
                bool v = (j < KTOT);
                int jc = v ? j : (KTOT - 1);
                cp16(kbase + (key * KSW + c * 4) * 4, Kg + (size_t)jc * HEADD + c * 8, v);
            }
            for (int i = tid; i < 1024; i += 256) {
                int d = i >> 3, c = i & 7;
                cp16(vbase + (d * VSW + c * 4) * 4, Vt + (size_t)d * VSTR + jn + c * 8, true);
            }
            cp_commit();
        }

        float bb[8][2];
#pragma unroll
        for (int nt = 0; nt < 8; nt++) {
            int ja = j0 + nt * 8 + cq * 2;
            bb[nt][0] = (ja < NSNW) ? g_bias[ja] : 0.f;
            bb[nt][1] = (ja + 1 < NSNW) ? g_bias[ja + 1] : 0.f;
        }

        // ---- S = Q @ K^T (8 k16-steps) ----
        float S[8][4];
#pragma unroll
        for (int nt = 0; nt < 8; nt++)
#pragma unroll
            for (int f = 0; f < 4; f++) S[nt][f] = 0.f;

#pragma unroll
        for (int s = 0; s < 8; s++) {
            const int kw = s * 8;
#pragma unroll
            for (int nt = 0; nt < 8; nt++) {
                uint32_t b0 = Ks[(nt * 8 + r0) * KSW + kw + cq];
                uint32_t b1 = Ks[(nt * 8 + r0) * KSW + kw + cq + 4];
                mma_f16(S[nt], QA[s][0], QA[s][1], QA[s][2], QA[s][3], b0, b1);
            }
        }

        // ---- online softmax ----
        float rm0 = neg_inf(), rm1 = neg_inf();
#pragma unroll
        for (int nt = 0; nt < 8; nt++) {
            int ja = j0 + nt * 8 + cq * 2;
            int jb = ja + 1;
            float s0 = (ja <= q0 + NSNW) ? S[nt][0] * ATTN_SCALE + bb[nt][0] : neg_inf();
            float s1 = (jb <= q0 + NSNW) ? S[nt][1] * ATTN_SCALE + bb[nt][1] : neg_inf();
            float s2 = (ja <= q1 + NSNW) ? S[nt][2] * ATTN_SCALE + bb[nt][0] : neg_inf();
            float s3 = (jb <= q1 + NSNW) ? S[nt][3] * ATTN_SCALE + bb[nt][1] : neg_inf();
            S[nt][0] = s0; S[nt][1] = s1; S[nt][2] = s2; S[nt][3] = s3;
            rm0 = fmaxf(rm0, fmaxf(s0, s1));
            rm1 = fmaxf(rm1, fmaxf(s2, s3));
        }
        rm0 = fmaxf(rm0, __shfl_xor_sync(0xffffffffu, rm0, 1));
        rm0 = fmaxf(rm0, __shfl_xor_sync(0xffffffffu, rm0, 2));
        rm1 = fmaxf(rm1, __shfl_xor_sync(0xffffffffu, rm1, 1));
        rm1 = fmaxf(rm1, __shfl_xor_sync(0xffffffffu, rm1, 2));

        float mn0 = fmaxf(m0, rm0);
        float mn1 = fmaxf(m1, rm1);
        float mns0 = (mn0 == neg_inf()) ? 0.f : mn0;
        float mns1 = (mn1 == neg_inf()) ? 0.f : mn1;
        float f0 = __expf(m0 - mns0);
        float f1 = __expf(m1 - mns1);
        if (m0 == neg_inf()) f0 = 0.f;
        if (m1 == neg_inf()) f1 = 0.f;
        m0 = mn0; m1 = mn1;
        l0 *= f0; l1 *= f1;
#pragma unroll
        for (int nt = 0; nt < 16; nt++) {
            O[nt][0] *= f0; O[nt][1] *= f0;
            O[nt][2] *= f1; O[nt][3] *= f1;
        }

        float ps0 = 0.f, ps1 = 0.f;
#pragma unroll
        for (int nt = 0; nt < 8; nt++) {
            float p0 = __expf(S[nt][0] - mns0);
            float p1 = __expf(S[nt][1] - mns0);
            float p2 = __expf(S[nt][2] - mns1);
            float p3 = __expf(S[nt][3] - mns1);
            ps0 += p0 + p1;
            ps1 += p2 + p3;
            Ps[(qw + r0) * PSW + nt * 4 + cq]     = f2h2(p0, p1);
            Ps[(qw + r0 + 8) * PSW + nt * 4 + cq] = f2h2(p2, p3);
        }
        ps0 += __shfl_xor_sync(0xffffffffu, ps0, 1);
        ps0 += __shfl_xor_sync(0xffffffffu, ps0, 2);
        ps1 += __shfl_xor_sync(0xffffffffu, ps1, 1);
        ps1 += __shfl_xor_sync(0xffffffffu, ps1, 2);
        l0 += ps0; l1 += ps1;

        __syncwarp();

        // ---- O += P @ V (4 k16-steps over 64 keys) ----
#pragma unroll
        for (int s = 0; s < 4; s++) {
            const int kw = s * 8;
            uint32_t a0 = Ps[(qw + r0) * PSW + kw + cq];
            uint32_t a1 = Ps[(qw + r0 + 8) * PSW + kw + cq];
            uint32_t a2 = Ps[(qw + r0) * PSW + kw + cq + 4];
            uint32_t a3 = Ps[(qw + r0 + 8) * PSW + kw + cq + 4];
#pragma unroll
            for (int nt = 0; nt < 16; nt++) {
                uint32_t b0 = Vs[(nt * 8 + r0) * VSW + kw + cq];
                uint32_t b1 = Vs[(nt * 8 + r0) * VSW + kw + cq + 4];
                mma_f16(O[nt], a0, a1, a2, a3, b0, b1);
            }
        }
    }

    // ---- normalize + write fp16 for Wo ----
    float inv0 = 1.f / l0, inv1 = 1.f / l1;
    uint32_t* oh = (uint32_t*)g_attnH;
    const size_t hb = (size_t)h * HEADD;
#pragma unroll
    for (int nt = 0; nt < 16; nt++) {
        int c = nt * 8 + cq * 2;
        oh[((size_t)q0 * DMODEL + hb + c) >> 1] = f2h2(O[nt][0] * inv0, O[nt][1] * inv0);
        oh[((size_t)q1 * DMODEL + hb + c) >> 1] = f2h2(O[nt][2] * inv1, O[nt][3] * inv1);
    }
}

// ---------------- launch ----------------
extern "C" void kernel_launch(void* const* d_in, const int* in_sizes, int n_in,
                              void* d_out, int out_size) {
    const float* hidden    = (const float*)d_in[0];
    const float* sink_k    = (const float*)d_in[1];
    const float* sink_v    = (const float*)d_in[2];
    const float* win_k     = (const float*)d_in[3];
    const float* win_v     = (const float*)d_in[4];
    const int*   sink_pos  = (const int*)d_in[5];
    const int*   key_pos   = (const int*)d_in[6];
    const float* sink_mask = (const float*)d_in[7];
    const float* key_mask  = (const float*)d_in[8];
    const float* Wq        = (const float*)d_in[9];
    const float* Wk        = (const float*)d_in[10];
    const float* Wv        = (const float*)d_in[11];
    const float* Wo        = (const float*)d_in[12];
    float*       out       = (float*)d_out;

    float *pq;
    __half *phidH, *pWqT, *pWkT, *pWvT, *pWoT, *pattnH;
    cudaGetSymbolAddress((void**)&pq, g_q);
    cudaGetSymbolAddress((void**)&phidH, g_hidH);
    cudaGetSymbolAddress((void**)&pWqT, g_WqT);
    cudaGetSymbolAddress((void**)&pWkT, g_WkT);
    cudaGetSymbolAddress((void**)&pWvT, g_WvT);
    cudaGetSymbolAddress((void**)&pWoT, g_WoT);
    cudaGetSymbolAddress((void**)&pattnH, g_attnH);

    static bool attr_set = false;
    if (!attr_set) {
        cudaFuncSetAttribute(attn_mma_kernel,
                             cudaFuncAttributeMaxDynamicSharedMemorySize,
                             ATTN_SMEM_BYTES);
        attr_set = true;
    }

    maxbias_kernel<<<1 + (NSNW + 255) / 256, 256>>>(sink_pos, key_pos, sink_mask, key_mask);

    // prep: fp16 operand copies
    h2h_kernel<<<QLEN * DMODEL / (256 * 8), 256>>>(hidden, phidH, QLEN * DMODEL);
    wtrans_kernel<<<dim3(DMODEL / 32, DMODEL / 32), 256>>>(Wq, pWqT, DMODEL);
    wtrans_kernel<<<dim3(KVDIM / 32, DMODEL / 32), 256>>>(Wk, pWkT, KVDIM);
    wtrans_kernel<<<dim3(KVDIM / 32, DMODEL / 32), 256>>>(Wv, pWvT, KVDIM);
    wtrans_kernel<<<dim3(DMODEL / 32, DMODEL / 32), 256>>>(Wo, pWoT, DMODEL);

    // projections (fp16 mma, 2 CTA/SM)
    gemm_f16<<<dim3(DMODEL / 128, QLEN / 128), 256>>>(phidH, pWqT, pq, DMODEL);
    gemm_f16_kv<<<dim3(16, QLEN / 128), 256>>>(phidH);

    // RoPE + K cache (fp16 out), V transpose (fp16 out)
    rope_build_kernel<<<ROPE_BLOCKS + BUILDK_BLOCKS, 256>>>(sink_k, win_k, sink_pos, key_pos);
    transpose_v_kernel<<<dim3((KTOT + 31) / 32, NKVH), 256>>>(sink_v, win_v);

    // attention (fp16 mma)
    attn_mma_kernel<<<dim3(NHEAD, QLEN / 128), 256, ATTN_SMEM_BYTES>>>();

    // output projection
    gemm_f16<<<dim3(DMODEL / 128, QLEN / 128), 256>>>(pattnH, pWoT, out, DMODEL);
}